// round 1
// baseline (speedup 1.0000x reference)
#include <cuda_runtime.h>
#include <math_constants.h>

#define DMODEL 1024
#define NHEADS 16
#define DKH    64
#define BATCH  2
#define SEQ    2048
#define NTOK   (BATCH*SEQ)     // 4096
#define NBH    (BATCH*NHEADS)  // 32
#define TOPK   512

// ---- scratch (static device globals; no runtime allocation) ----
__device__ float g_Q[(size_t)NTOK * DMODEL];
__device__ float g_K[(size_t)NTOK * DMODEL];
__device__ float g_V[(size_t)NTOK * DMODEL];
__device__ float g_ctx[(size_t)NTOK * DMODEL];
__device__ float g_S[(size_t)NBH * SEQ * SEQ];   // 512 MiB score/prob matrix

// ============================================================================
// Generic NN SGEMM with bias: C[M,N] = A[M,K] @ B[K,N] + bias
// BM=BN=128, BK=8, 256 threads, 8x8 per-thread tile.
// ============================================================================
__global__ __launch_bounds__(256)
void sgemm_nn_bias(const float* __restrict__ A, const float* __restrict__ Bm,
                   const float* __restrict__ bias, float* __restrict__ C,
                   int M, int N, int K)
{
    __shared__ float As[8][128];
    __shared__ float Bs[8][128];
    const int tid = threadIdx.x;
    const int tx = tid & 15;        // 0..15 -> 8 cols each
    const int ty = tid >> 4;        // 0..15 -> 8 rows each
    const int m0 = blockIdx.y * 128;
    const int n0 = blockIdx.x * 128;

    float acc[8][8];
    #pragma unroll
    for (int i = 0; i < 8; i++)
        #pragma unroll
        for (int j = 0; j < 8; j++) acc[i][j] = 0.f;

    for (int k0 = 0; k0 < K; k0 += 8) {
        {   // A tile 128x8, transposed into As[k][m]
            int r  = tid >> 1;
            int kq = (tid & 1) * 4;
            float4 v = *(const float4*)(A + (size_t)(m0 + r) * K + k0 + kq);
            As[kq+0][r] = v.x; As[kq+1][r] = v.y; As[kq+2][r] = v.z; As[kq+3][r] = v.w;
        }
        {   // B tile 8x128
            int r = tid >> 5;
            int c = (tid & 31) * 4;
            *(float4*)&Bs[r][c] = *(const float4*)(Bm + (size_t)(k0 + r) * N + n0 + c);
        }
        __syncthreads();
        #pragma unroll
        for (int kk = 0; kk < 8; kk++) {
            float ra[8], rb[8];
            *(float4*)&ra[0] = *(float4*)&As[kk][ty*8];
            *(float4*)&ra[4] = *(float4*)&As[kk][ty*8+4];
            *(float4*)&rb[0] = *(float4*)&Bs[kk][tx*8];
            *(float4*)&rb[4] = *(float4*)&Bs[kk][tx*8+4];
            #pragma unroll
            for (int i = 0; i < 8; i++)
                #pragma unroll
                for (int j = 0; j < 8; j++) acc[i][j] += ra[i] * rb[j];
        }
        __syncthreads();
    }

    #pragma unroll
    for (int i = 0; i < 8; i++) {
        int m = m0 + ty*8 + i;
        #pragma unroll
        for (int j = 0; j < 8; j += 4) {
            int n = n0 + tx*8 + j;
            float4 o;
            o.x = acc[i][j+0] + bias[n+0];
            o.y = acc[i][j+1] + bias[n+1];
            o.z = acc[i][j+2] + bias[n+2];
            o.w = acc[i][j+3] + bias[n+3];
            *(float4*)(C + (size_t)m * N + n) = o;
        }
    }
}

// ============================================================================
// Scores: per (b,h)  S[q,k] = (1/8) * dot(Q[q,:], K[k,:])   (NT gemm, depth 64)
// grid: (k-tiles=16, q-tiles=16, bh=32)
// ============================================================================
__global__ __launch_bounds__(256)
void scores_kernel(const float* __restrict__ Qp, const float* __restrict__ Kp,
                   float* __restrict__ S)
{
    __shared__ float As[8][128];
    __shared__ float Bs[8][128];
    const int bz = blockIdx.z;
    const int b = bz >> 4, h = bz & 15;
    const float* Aq = Qp + (size_t)b * SEQ * DMODEL + h * DKH;
    const float* Bk = Kp + (size_t)b * SEQ * DMODEL + h * DKH;
    const int tid = threadIdx.x;
    const int tx = tid & 15, ty = tid >> 4;
    const int q0 = blockIdx.y * 128;
    const int k0v = blockIdx.x * 128;

    float acc[8][8];
    #pragma unroll
    for (int i = 0; i < 8; i++)
        #pragma unroll
        for (int j = 0; j < 8; j++) acc[i][j] = 0.f;

    for (int e0 = 0; e0 < DKH; e0 += 8) {
        int r  = tid >> 1;
        int kq = (tid & 1) * 4;
        float4 va = *(const float4*)(Aq + (size_t)(q0 + r) * DMODEL + e0 + kq);
        As[kq+0][r] = va.x; As[kq+1][r] = va.y; As[kq+2][r] = va.z; As[kq+3][r] = va.w;
        float4 vb = *(const float4*)(Bk + (size_t)(k0v + r) * DMODEL + e0 + kq);
        Bs[kq+0][r] = vb.x; Bs[kq+1][r] = vb.y; Bs[kq+2][r] = vb.z; Bs[kq+3][r] = vb.w;
        __syncthreads();
        #pragma unroll
        for (int kk = 0; kk < 8; kk++) {
            float ra[8], rb[8];
            *(float4*)&ra[0] = *(float4*)&As[kk][ty*8];
            *(float4*)&ra[4] = *(float4*)&As[kk][ty*8+4];
            *(float4*)&rb[0] = *(float4*)&Bs[kk][tx*8];
            *(float4*)&rb[4] = *(float4*)&Bs[kk][tx*8+4];
            #pragma unroll
            for (int i = 0; i < 8; i++)
                #pragma unroll
                for (int j = 0; j < 8; j++) acc[i][j] += ra[i] * rb[j];
        }
        __syncthreads();
    }

    const float scale = 0.125f;   // 1/sqrt(64)
    float* Sb = S + (size_t)bz * SEQ * SEQ;
    #pragma unroll
    for (int i = 0; i < 8; i++) {
        int q = q0 + ty*8 + i;
        #pragma unroll
        for (int j = 0; j < 8; j += 4) {
            int k = k0v + tx*8 + j;
            float4 o;
            o.x = acc[i][j+0] * scale;
            o.y = acc[i][j+1] * scale;
            o.z = acc[i][j+2] * scale;
            o.w = acc[i][j+3] * scale;
            *(float4*)(Sb + (size_t)q * SEQ + k) = o;
        }
    }
}

// ============================================================================
// Per-row: exact radix-select of 512th-largest score, masked softmax,
// write normalized sparse probabilities back in place.
// One block (256 thr) per row; grid = NBH*SEQ = 65536 rows.
// ============================================================================
__device__ __forceinline__ unsigned int f2k(float f) {
    unsigned int b = __float_as_uint(f);
    return (b & 0x80000000u) ? ~b : (b | 0x80000000u);
}

__global__ __launch_bounds__(256)
void topk_softmax_kernel(float* __restrict__ S)
{
    __shared__ float row[SEQ];
    __shared__ unsigned int hist[256];
    __shared__ float red[256];
    __shared__ unsigned int sh_prefix;
    __shared__ int sh_kk;

    const int tid = threadIdx.x;
    float* Srow = S + (size_t)blockIdx.x * SEQ;

    // load row + running max
    float m = -CUDART_INF_F;
    #pragma unroll
    for (int i = 0; i < 8; i++) {
        float f = Srow[tid + i*256];
        row[tid + i*256] = f;
        m = fmaxf(m, f);
    }
    red[tid] = m;
    __syncthreads();
    for (int s = 128; s > 0; s >>= 1) {
        if (tid < s) red[tid] = fmaxf(red[tid], red[tid + s]);
        __syncthreads();
    }
    const float rowmax = red[0];
    __syncthreads();   // everyone has rowmax before red is reused

    // 4-pass MSB radix select for the TOPK-th largest value (exact bits)
    unsigned int prefix = 0, prefmask = 0;
    int kk = TOPK;
    #pragma unroll
    for (int pass = 0; pass < 4; pass++) {
        const int shift = 24 - 8*pass;
        hist[tid] = 0;
        __syncthreads();
        #pragma unroll
        for (int i = 0; i < 8; i++) {
            unsigned int key = f2k(row[tid + i*256]);
            if ((key & prefmask) == prefix)
                atomicAdd(&hist[(key >> shift) & 255u], 1u);
        }
        __syncthreads();
        if (tid == 0) {
            int cum = 0, d = 255;
            for (; d > 0; d--) {
                int c = (int)hist[d];
                if (cum + c >= kk) break;
                cum += c;
            }
            sh_prefix = prefix | ((unsigned int)d << shift);
            sh_kk = kk - cum;
        }
        __syncthreads();
        prefix = sh_prefix;
        kk = sh_kk;
        prefmask |= (0xFFu << shift);
        __syncthreads();
    }
    const unsigned int tkey = prefix;   // exact key of 512th largest

    // masked softmax (exp only where selected), normalize, write back
    float lsum = 0.f;
    #pragma unroll
    for (int i = 0; i < 8; i++) {
        int idx = tid + i*256;
        float f = row[idx];
        float p = (f2k(f) >= tkey) ? __expf(f - rowmax) : 0.f;
        row[idx] = p;
        lsum += p;
    }
    red[tid] = lsum;
    __syncthreads();
    for (int s = 128; s > 0; s >>= 1) {
        if (tid < s) red[tid] += red[tid + s];
        __syncthreads();
    }
    const float inv = 1.0f / red[0];
    #pragma unroll
    for (int i = 0; i < 8; i++) {
        int idx = tid + i*256;
        Srow[idx] = row[idx] * inv;
    }
}

// ============================================================================
// context = P @ V per (b,h): (2048x2048)@(2048x64) -> ctx[(b,q), h*64+e]
// BM=128, BN=64, BK=16, 256 threads, 8x4 per-thread tile.
// grid: (q-tiles=16, bh=32)
// ============================================================================
__global__ __launch_bounds__(256)
void av_kernel(const float* __restrict__ S, const float* __restrict__ Vp,
               float* __restrict__ ctx)
{
    __shared__ float Ps[16][128];
    __shared__ float Vs[16][64];
    const int bz = blockIdx.y;
    const int b = bz >> 4, h = bz & 15;
    const float* Sb = S + (size_t)bz * SEQ * SEQ;
    const float* Vb = Vp + (size_t)b * SEQ * DMODEL + h * DKH;
    const int tid = threadIdx.x;
    const int tx = tid & 15;   // 0..15 -> 4 cols
    const int ty = tid >> 4;   // 0..15 -> 8 rows
    const int q0 = blockIdx.x * 128;

    float acc[8][4];
    #pragma unroll
    for (int i = 0; i < 8; i++)
        #pragma unroll
        for (int j = 0; j < 4; j++) acc[i][j] = 0.f;

    for (int k0 = 0; k0 < SEQ; k0 += 16) {
        {   // P tile 128x16, transposed
            int r  = tid >> 2;         // 0..63
            int kq = (tid & 3) * 4;
            float4 v  = *(const float4*)(Sb + (size_t)(q0 + r) * SEQ + k0 + kq);
            Ps[kq+0][r] = v.x; Ps[kq+1][r] = v.y; Ps[kq+2][r] = v.z; Ps[kq+3][r] = v.w;
            float4 v2 = *(const float4*)(Sb + (size_t)(q0 + r + 64) * SEQ + k0 + kq);
            Ps[kq+0][r+64] = v2.x; Ps[kq+1][r+64] = v2.y; Ps[kq+2][r+64] = v2.z; Ps[kq+3][r+64] = v2.w;
        }
        {   // V tile 16x64
            int r = tid >> 4;
            int c = (tid & 15) * 4;
            *(float4*)&Vs[r][c] = *(const float4*)(Vb + (size_t)(k0 + r) * DMODEL + c);
        }
        __syncthreads();
        #pragma unroll
        for (int kk = 0; kk < 16; kk++) {
            float ra[8], rb[4];
            *(float4*)&ra[0] = *(float4*)&Ps[kk][ty*8];
            *(float4*)&ra[4] = *(float4*)&Ps[kk][ty*8+4];
            *(float4*)&rb[0] = *(float4*)&Vs[kk][tx*4];
            #pragma unroll
            for (int i = 0; i < 8; i++)
                #pragma unroll
                for (int j = 0; j < 4; j++) acc[i][j] += ra[i] * rb[j];
        }
        __syncthreads();
    }

    #pragma unroll
    for (int i = 0; i < 8; i++) {
        int q = q0 + ty*8 + i;
        float4 o;
        o.x = acc[i][0]; o.y = acc[i][1]; o.z = acc[i][2]; o.w = acc[i][3];
        *(float4*)(ctx + (size_t)(b * SEQ + q) * DMODEL + h * DKH + tx*4) = o;
    }
}

// ============================================================================
// launch
// ============================================================================
extern "C" void kernel_launch(void* const* d_in, const int* in_sizes, int n_in,
                              void* d_out, int out_size)
{
    (void)in_sizes; (void)n_in; (void)out_size;
    const float* queries = (const float*)d_in[0];
    const float* keys    = (const float*)d_in[1];
    const float* values  = (const float*)d_in[2];
    const float* Wq = (const float*)d_in[3];
    const float* bq = (const float*)d_in[4];
    const float* Wk = (const float*)d_in[5];
    const float* bk = (const float*)d_in[6];
    const float* Wv = (const float*)d_in[7];
    const float* bv = (const float*)d_in[8];
    const float* Wo = (const float*)d_in[9];
    const float* bo = (const float*)d_in[10];
    float* out = (float*)d_out;

    float *gQ, *gK, *gV, *gctx, *gS;
    cudaGetSymbolAddress((void**)&gQ,   g_Q);
    cudaGetSymbolAddress((void**)&gK,   g_K);
    cudaGetSymbolAddress((void**)&gV,   g_V);
    cudaGetSymbolAddress((void**)&gctx, g_ctx);
    cudaGetSymbolAddress((void**)&gS,   g_S);

    dim3 gProj(DMODEL/128, NTOK/128);      // (8, 32)
    sgemm_nn_bias<<<gProj, 256>>>(queries, Wq, bq, gQ, NTOK, DMODEL, DMODEL);
    sgemm_nn_bias<<<gProj, 256>>>(keys,    Wk, bk, gK, NTOK, DMODEL, DMODEL);
    sgemm_nn_bias<<<gProj, 256>>>(values,  Wv, bv, gV, NTOK, DMODEL, DMODEL);

    dim3 gScores(SEQ/128, SEQ/128, NBH);   // (16, 16, 32)
    scores_kernel<<<gScores, 256>>>(gQ, gK, gS);

    topk_softmax_kernel<<<NBH * SEQ, 256>>>(gS);

    dim3 gAV(SEQ/128, NBH);                // (16, 32)
    av_kernel<<<gAV, 256>>>(gS, gV, gctx);

    sgemm_nn_bias<<<gProj, 256>>>(gctx, Wo, bo, out, NTOK, DMODEL, DMODEL);
}

// round 11
// speedup vs baseline: 1.1156x; 1.1156x over previous
#include <cuda_runtime.h>

#define DMODEL 1024
#define NHEADS 16
#define DKH    64
#define BATCH  2
#define SEQ    2048
#define NTOK   (BATCH*SEQ)
#define NBH    (BATCH*NHEADS)
#define TOPK   512
#define LDSM   24

/* GEMM tile config (BM=128 BN=64, 4 warps 2x2) */
#define GBM 128
#define GBN 64
#define GWM 64
#define GWN 32
#define GMI 4
#define GNI 4
#define GNJ 2
#define GNA 2
#define GNB 1

/* bf16 stored as raw unsigned short (no cuda_bf16.h) */

/* ---------------- scratch (static device globals) ---------------- */
__device__ float g_f32[(size_t)NTOK * DMODEL];
__device__ float g_S[(size_t)NBH * SEQ * SEQ];
__device__ unsigned short g_inhi[(size_t)NTOK * DMODEL];
__device__ unsigned short g_inmd[(size_t)NTOK * DMODEL];
__device__ unsigned short g_inlo[(size_t)NTOK * DMODEL];
__device__ unsigned short g_wthi[(size_t)DMODEL * DMODEL];
__device__ unsigned short g_wtmd[(size_t)DMODEL * DMODEL];
__device__ unsigned short g_wtlo[(size_t)DMODEL * DMODEL];
__device__ unsigned short g_qhi[(size_t)NTOK * DMODEL];
__device__ unsigned short g_qmd[(size_t)NTOK * DMODEL];
__device__ unsigned short g_qlo[(size_t)NTOK * DMODEL];
__device__ unsigned short g_khi[(size_t)NTOK * DMODEL];
__device__ unsigned short g_kmd[(size_t)NTOK * DMODEL];
__device__ unsigned short g_klo[(size_t)NTOK * DMODEL];
__device__ unsigned short g_vthi[(size_t)NBH * DKH * SEQ];
__device__ unsigned short g_vtlo[(size_t)NBH * DKH * SEQ];
__device__ unsigned short g_phi[(size_t)NBH * SEQ * SEQ];
__device__ unsigned short g_plo[(size_t)NBH * SEQ * SEQ];

/* ---------------- bf16 conversion helpers (round-to-nearest-even) -------- */
__device__ __forceinline__ unsigned short f2bf(float f)
{
    unsigned int u = __float_as_uint(f);
    unsigned int r = u + 0x7FFFu + ((u >> 16) & 1u);
    return (unsigned short)(r >> 16);
}

__device__ __forceinline__ float bf2f(unsigned short h)
{
    return __uint_as_float(((unsigned int)h) << 16);
}

/* ---------------- mma / ldmatrix helpers ---------------- */
__device__ __forceinline__ void ldm4(unsigned int* r, const void* p)
{
    unsigned int a = (unsigned int)__cvta_generic_to_shared(p);
    asm volatile("ldmatrix.sync.aligned.m8n8.x4.shared.b16 {%0,%1,%2,%3},[%4];"
        : "=r"(r[0]), "=r"(r[1]), "=r"(r[2]), "=r"(r[3]) : "r"(a));
}

__device__ __forceinline__ void mma16816(float* d, const unsigned int* a,
                                         unsigned int b0, unsigned int b1)
{
    asm volatile("mma.sync.aligned.m16n8k16.row.col.f32.bf16.bf16.f32 "
        "{%0,%1,%2,%3},{%4,%5,%6,%7},{%8,%9},{%0,%1,%2,%3};"
        : "+f"(d[0]), "+f"(d[1]), "+f"(d[2]), "+f"(d[3])
        : "r"(a[0]), "r"(a[1]), "r"(a[2]), "r"(a[3]), "r"(b0), "r"(b1));
}

/* ============================================================================
   NT bf16x4 GEMM (2-way split, 4 products): smooth-error path (Vproj/AV/Oproj)
   ========================================================================= */
__global__ __launch_bounds__(128)
void gemm_bf16x4_nt(const unsigned short* __restrict__ Ahi,
                    const unsigned short* __restrict__ Alo,
                    const unsigned short* __restrict__ Bhi,
                    const unsigned short* __restrict__ Blo,
                    const float* __restrict__ bias, float* __restrict__ C,
                    int K, int lda, int ldb, int ldc,
                    long long sAb, long long sAh, long long sBb, long long sBh,
                    long long sCb, long long sCh, int HS)
{
    __shared__ unsigned short sA[2][2][GBM][LDSM];
    __shared__ unsigned short sB[2][2][GBN][LDSM];

    const int tid  = threadIdx.x;
    const int warp = tid >> 5;
    const int lane = tid & 31;
    const int wm   = warp >> 1;
    const int wn   = warp & 1;
    const int bz   = blockIdx.z;
    const int bb   = bz / HS;
    const int hh   = bz % HS;

    const unsigned short* Ah = Ahi + (size_t)bb * sAb + (size_t)hh * sAh + (size_t)blockIdx.y * GBM * lda;
    const unsigned short* Al = Alo + (size_t)bb * sAb + (size_t)hh * sAh + (size_t)blockIdx.y * GBM * lda;
    const unsigned short* Bh = Bhi + (size_t)bb * sBb + (size_t)hh * sBh + (size_t)blockIdx.x * GBN * ldb;
    const unsigned short* Bl = Blo + (size_t)bb * sBb + (size_t)hh * sBh + (size_t)blockIdx.x * GBN * ldb;

    float acc[GMI][GNI][4];
    #pragma unroll
    for (int i = 0; i < GMI; i++) {
        #pragma unroll
        for (int j = 0; j < GNI; j++) {
            acc[i][j][0] = 0.f; acc[i][j][1] = 0.f;
            acc[i][j][2] = 0.f; acc[i][j][3] = 0.f;
        }
    }

    uint4 rah[GNA], ral[GNA], rbh[GNB], rbl[GNB];
    const int KT = K / 16;

    #pragma unroll
    for (int i = 0; i < GNA; i++) {
        int idx = tid + i * 128;
        int r = idx >> 1;
        int c = idx & 1;
        rah[i] = *(const uint4*)(Ah + (size_t)r * lda + c * 8);
        ral[i] = *(const uint4*)(Al + (size_t)r * lda + c * 8);
    }
    #pragma unroll
    for (int i = 0; i < GNB; i++) {
        int idx = tid + i * 128;
        int r = idx >> 1;
        int c = idx & 1;
        rbh[i] = *(const uint4*)(Bh + (size_t)r * ldb + c * 8);
        rbl[i] = *(const uint4*)(Bl + (size_t)r * ldb + c * 8);
    }
    #pragma unroll
    for (int i = 0; i < GNA; i++) {
        int idx = tid + i * 128;
        int r = idx >> 1;
        int c = idx & 1;
        *(uint4*)&sA[0][0][r][c * 8] = rah[i];
        *(uint4*)&sA[0][1][r][c * 8] = ral[i];
    }
    #pragma unroll
    for (int i = 0; i < GNB; i++) {
        int idx = tid + i * 128;
        int r = idx >> 1;
        int c = idx & 1;
        *(uint4*)&sB[0][0][r][c * 8] = rbh[i];
        *(uint4*)&sB[0][1][r][c * 8] = rbl[i];
    }
    __syncthreads();

    for (int kt = 0; kt < KT; kt++) {
        int buf = kt & 1;
        int more = (kt + 1 < KT) ? 1 : 0;

        if (more) {
            int k0 = (kt + 1) * 16;
            #pragma unroll
            for (int i = 0; i < GNA; i++) {
                int idx = tid + i * 128;
                int r = idx >> 1;
                int c = idx & 1;
                rah[i] = *(const uint4*)(Ah + (size_t)r * lda + k0 + c * 8);
                ral[i] = *(const uint4*)(Al + (size_t)r * lda + k0 + c * 8);
            }
            #pragma unroll
            for (int i = 0; i < GNB; i++) {
                int idx = tid + i * 128;
                int r = idx >> 1;
                int c = idx & 1;
                rbh[i] = *(const uint4*)(Bh + (size_t)r * ldb + k0 + c * 8);
                rbl[i] = *(const uint4*)(Bl + (size_t)r * ldb + k0 + c * 8);
            }
        }

        {
            unsigned int fah[GMI][4], fal[GMI][4], fbh2[GNJ][4], fbl2[GNJ][4];
            #pragma unroll
            for (int mi = 0; mi < GMI; mi++) {
                ldm4(fah[mi], &sA[buf][0][wm * GWM + mi * 16 + (lane & 15)][(lane >> 4) * 8]);
                ldm4(fal[mi], &sA[buf][1][wm * GWM + mi * 16 + (lane & 15)][(lane >> 4) * 8]);
            }
            #pragma unroll
            for (int nj = 0; nj < GNJ; nj++) {
                ldm4(fbh2[nj], &sB[buf][0][wn * GWN + nj * 16 + (lane & 15)][(lane >> 4) * 8]);
                ldm4(fbl2[nj], &sB[buf][1][wn * GWN + nj * 16 + (lane & 15)][(lane >> 4) * 8]);
            }
            #pragma unroll
            for (int mi = 0; mi < GMI; mi++) {
                #pragma unroll
                for (int nj = 0; nj < GNJ; nj++) {
                    float* c0 = acc[mi][2 * nj];
                    float* c1 = acc[mi][2 * nj + 1];
                    mma16816(c0, fah[mi], fbh2[nj][0], fbh2[nj][2]);
                    mma16816(c0, fah[mi], fbl2[nj][0], fbl2[nj][2]);
                    mma16816(c0, fal[mi], fbh2[nj][0], fbh2[nj][2]);
                    mma16816(c0, fal[mi], fbl2[nj][0], fbl2[nj][2]);
                    mma16816(c1, fah[mi], fbh2[nj][1], fbh2[nj][3]);
                    mma16816(c1, fah[mi], fbl2[nj][1], fbl2[nj][3]);
                    mma16816(c1, fal[mi], fbh2[nj][1], fbh2[nj][3]);
                    mma16816(c1, fal[mi], fbl2[nj][1], fbl2[nj][3]);
                }
            }
        }

        if (more) {
            int nb = buf ^ 1;
            #pragma unroll
            for (int i = 0; i < GNA; i++) {
                int idx = tid + i * 128;
                int r = idx >> 1;
                int c = idx & 1;
                *(uint4*)&sA[nb][0][r][c * 8] = rah[i];
                *(uint4*)&sA[nb][1][r][c * 8] = ral[i];
            }
            #pragma unroll
            for (int i = 0; i < GNB; i++) {
                int idx = tid + i * 128;
                int r = idx >> 1;
                int c = idx & 1;
                *(uint4*)&sB[nb][0][r][c * 8] = rbh[i];
                *(uint4*)&sB[nb][1][r][c * 8] = rbl[i];
            }
        }
        __syncthreads();
    }

    float* Cp = C + (size_t)bb * sCb + (size_t)hh * sCh;
    const int m0 = blockIdx.y * GBM + wm * GWM;
    const int n0 = blockIdx.x * GBN + wn * GWN;
    #pragma unroll
    for (int mi = 0; mi < GMI; mi++) {
        #pragma unroll
        for (int ni = 0; ni < GNI; ni++) {
            int row = m0 + mi * 16 + (lane >> 2);
            int col = n0 + ni * 8 + (lane & 3) * 2;
            float b0 = 0.f;
            float b1 = 0.f;
            if (bias) {
                b0 = bias[col];
                b1 = bias[col + 1];
            }
            Cp[(size_t)row * ldc + col]           = acc[mi][ni][0] + b0;
            Cp[(size_t)row * ldc + col + 1]       = acc[mi][ni][1] + b1;
            Cp[(size_t)(row + 8) * ldc + col]     = acc[mi][ni][2] + b0;
            Cp[(size_t)(row + 8) * ldc + col + 1] = acc[mi][ni][3] + b1;
        }
    }
}

/* ============================================================================
   NT bf16x6 GEMM (3-way split hi/mid/lo, 6 products): selection-critical path
   (Q-proj, K-proj, scores). Single-buffered smem (3 planes), reg prefetch.
   Error: rep ~2^-26, dominated by fp32 accumulation (~1e-6) -> fp32-class.
   ========================================================================= */
__global__ __launch_bounds__(128)
void gemm_bf16x6_nt(const unsigned short* __restrict__ Ahi,
                    const unsigned short* __restrict__ Amd,
                    const unsigned short* __restrict__ Alo,
                    const unsigned short* __restrict__ Bhi,
                    const unsigned short* __restrict__ Bmd,
                    const unsigned short* __restrict__ Blo,
                    const float* __restrict__ bias, float* __restrict__ C,
                    int K, int lda, int ldb, int ldc,
                    long long sAb, long long sAh, long long sBb, long long sBh,
                    long long sCb, long long sCh, int HS)
{
    __shared__ unsigned short sA[3][GBM][LDSM];
    __shared__ unsigned short sB[3][GBN][LDSM];

    const int tid  = threadIdx.x;
    const int warp = tid >> 5;
    const int lane = tid & 31;
    const int wm   = warp >> 1;
    const int wn   = warp & 1;
    const int bz   = blockIdx.z;
    const int bb   = bz / HS;
    const int hh   = bz % HS;

    const unsigned short* Ah = Ahi + (size_t)bb * sAb + (size_t)hh * sAh + (size_t)blockIdx.y * GBM * lda;
    const unsigned short* Am = Amd + (size_t)bb * sAb + (size_t)hh * sAh + (size_t)blockIdx.y * GBM * lda;
    const unsigned short* Al = Alo + (size_t)bb * sAb + (size_t)hh * sAh + (size_t)blockIdx.y * GBM * lda;
    const unsigned short* Bh = Bhi + (size_t)bb * sBb + (size_t)hh * sBh + (size_t)blockIdx.x * GBN * ldb;
    const unsigned short* Bm = Bmd + (size_t)bb * sBb + (size_t)hh * sBh + (size_t)blockIdx.x * GBN * ldb;
    const unsigned short* Bl = Blo + (size_t)bb * sBb + (size_t)hh * sBh + (size_t)blockIdx.x * GBN * ldb;

    float acc[GMI][GNI][4];
    #pragma unroll
    for (int i = 0; i < GMI; i++) {
        #pragma unroll
        for (int j = 0; j < GNI; j++) {
            acc[i][j][0] = 0.f; acc[i][j][1] = 0.f;
            acc[i][j][2] = 0.f; acc[i][j][3] = 0.f;
        }
    }

    uint4 rah[GNA], ram[GNA], ral[GNA], rbh[GNB], rbm[GNB], rbl[GNB];
    const int KT = K / 16;

    /* prologue: tile 0 -> regs -> smem */
    #pragma unroll
    for (int i = 0; i < GNA; i++) {
        int idx = tid + i * 128;
        int r = idx >> 1;
        int c = idx & 1;
        rah[i] = *(const uint4*)(Ah + (size_t)r * lda + c * 8);
        ram[i] = *(const uint4*)(Am + (size_t)r * lda + c * 8);
        ral[i] = *(const uint4*)(Al + (size_t)r * lda + c * 8);
    }
    #pragma unroll
    for (int i = 0; i < GNB; i++) {
        int idx = tid + i * 128;
        int r = idx >> 1;
        int c = idx & 1;
        rbh[i] = *(const uint4*)(Bh + (size_t)r * ldb + c * 8);
        rbm[i] = *(const uint4*)(Bm + (size_t)r * ldb + c * 8);
        rbl[i] = *(const uint4*)(Bl + (size_t)r * ldb + c * 8);
    }
    #pragma unroll
    for (int i = 0; i < GNA; i++) {
        int idx = tid + i * 128;
        int r = idx >> 1;
        int c = idx & 1;
        *(uint4*)&sA[0][r][c * 8] = rah[i];
        *(uint4*)&sA[1][r][c * 8] = ram[i];
        *(uint4*)&sA[2][r][c * 8] = ral[i];
    }
    #pragma unroll
    for (int i = 0; i < GNB; i++) {
        int idx = tid + i * 128;
        int r = idx >> 1;
        int c = idx & 1;
        *(uint4*)&sB[0][r][c * 8] = rbh[i];
        *(uint4*)&sB[1][r][c * 8] = rbm[i];
        *(uint4*)&sB[2][r][c * 8] = rbl[i];
    }
    __syncthreads();

    for (int kt = 0; kt < KT; kt++) {
        int more = (kt + 1 < KT) ? 1 : 0;

        if (more) {
            int k0 = (kt + 1) * 16;
            #pragma unroll
            for (int i = 0; i < GNA; i++) {
                int idx = tid + i * 128;
                int r = idx >> 1;
                int c = idx & 1;
                rah[i] = *(const uint4*)(Ah + (size_t)r * lda + k0 + c * 8);
                ram[i] = *(const uint4*)(Am + (size_t)r * lda + k0 + c * 8);
                ral[i] = *(const uint4*)(Al + (size_t)r * lda + k0 + c * 8);
            }
            #pragma unroll
            for (int i = 0; i < GNB; i++) {
                int idx = tid + i * 128;
                int r = idx >> 1;
                int c = idx & 1;
                rbh[i] = *(const uint4*)(Bh + (size_t)r * ldb + k0 + c * 8);
                rbm[i] = *(const uint4*)(Bm + (size_t)r * ldb + k0 + c * 8);
                rbl[i] = *(const uint4*)(Bl + (size_t)r * ldb + k0 + c * 8);
            }
        }

        {
            unsigned int fah[GMI][4], fam[GMI][4], fal[GMI][4];
            unsigned int fbh2[GNJ][4], fbm2[GNJ][4], fbl2[GNJ][4];
            #pragma unroll
            for (int mi = 0; mi < GMI; mi++) {
                ldm4(fah[mi], &sA[0][wm * GWM + mi * 16 + (lane & 15)][(lane >> 4) * 8]);
                ldm4(fam[mi], &sA[1][wm * GWM + mi * 16 + (lane & 15)][(lane >> 4) * 8]);
                ldm4(fal[mi], &sA[2][wm * GWM + mi * 16 + (lane & 15)][(lane >> 4) * 8]);
            }
            #pragma unroll
            for (int nj = 0; nj < GNJ; nj++) {
                ldm4(fbh2[nj], &sB[0][wn * GWN + nj * 16 + (lane & 15)][(lane >> 4) * 8]);
                ldm4(fbm2[nj], &sB[1][wn * GWN + nj * 16 + (lane & 15)][(lane >> 4) * 8]);
                ldm4(fbl2[nj], &sB[2][wn * GWN + nj * 16 + (lane & 15)][(lane >> 4) * 8]);
            }
            #pragma unroll
            for (int mi = 0; mi < GMI; mi++) {
                #pragma unroll
                for (int nj = 0; nj < GNJ; nj++) {
                    float* c0 = acc[mi][2 * nj];
                    float* c1 = acc[mi][2 * nj + 1];
                    /* hh + hm + mh + hl + mm + lh */
                    mma16816(c0, fah[mi], fbh2[nj][0], fbh2[nj][2]);
                    mma16816(c0, fah[mi], fbm2[nj][0], fbm2[nj][2]);
                    mma16816(c0, fam[mi], fbh2[nj][0], fbh2[nj][2]);
                    mma16816(c0, fah[mi], fbl2[nj][0], fbl2[nj][2]);
                    mma16816(c0, fam[mi], fbm2[nj][0], fbm2[nj][2]);
                    mma16816(c0, fal[mi], fbh2[nj][0], fbh2[nj][2]);
                    mma16816(c1, fah[mi], fbh2[nj][1], fbh2[nj][3]);
                    mma16816(c1, fah[mi], fbm2[nj][1], fbm2[nj][3]);
                    mma16816(c1, fam[mi], fbh2[nj][1], fbh2[nj][3]);
                    mma16816(c1, fah[mi], fbl2[nj][1], fbl2[nj][3]);
                    mma16816(c1, fam[mi], fbm2[nj][1], fbm2[nj][3]);
                    mma16816(c1, fal[mi], fbh2[nj][1], fbh2[nj][3]);
                }
            }
        }
        __syncthreads();

        if (more) {
            #pragma unroll
            for (int i = 0; i < GNA; i++) {
                int idx = tid + i * 128;
                int r = idx >> 1;
                int c = idx & 1;
                *(uint4*)&sA[0][r][c * 8] = rah[i];
                *(uint4*)&sA[1][r][c * 8] = ram[i];
                *(uint4*)&sA[2][r][c * 8] = ral[i];
            }
            #pragma unroll
            for (int i = 0; i < GNB; i++) {
                int idx = tid + i * 128;
                int r = idx >> 1;
                int c = idx & 1;
                *(uint4*)&sB[0][r][c * 8] = rbh[i];
                *(uint4*)&sB[1][r][c * 8] = rbm[i];
                *(uint4*)&sB[2][r][c * 8] = rbl[i];
            }
            __syncthreads();
        }
    }

    float* Cp = C + (size_t)bb * sCb + (size_t)hh * sCh;
    const int m0 = blockIdx.y * GBM + wm * GWM;
    const int n0 = blockIdx.x * GBN + wn * GWN;
    #pragma unroll
    for (int mi = 0; mi < GMI; mi++) {
        #pragma unroll
        for (int ni = 0; ni < GNI; ni++) {
            int row = m0 + mi * 16 + (lane >> 2);
            int col = n0 + ni * 8 + (lane & 3) * 2;
            float b0 = 0.f;
            float b1 = 0.f;
            if (bias) {
                b0 = bias[col];
                b1 = bias[col + 1];
            }
            Cp[(size_t)row * ldc + col]           = acc[mi][ni][0] + b0;
            Cp[(size_t)row * ldc + col + 1]       = acc[mi][ni][1] + b1;
            Cp[(size_t)(row + 8) * ldc + col]     = acc[mi][ni][2] + b0;
            Cp[(size_t)(row + 8) * ldc + col + 1] = acc[mi][ni][3] + b1;
        }
    }
}

/* ---------------- elementwise 2-way hi/lo split ---------------- */
__global__ __launch_bounds__(256)
void split_kernel(const float* __restrict__ x, unsigned short* __restrict__ hi,
                  unsigned short* __restrict__ lo, float scale, size_t n)
{
    size_t i = (size_t)blockIdx.x * 256 + threadIdx.x;
    if (i < n) {
        float v = x[i] * scale;
        unsigned short h = f2bf(v);
        hi[i] = h;
        lo[i] = f2bf(v - bf2f(h));
    }
}

/* ---------------- elementwise 3-way hi/mid/lo split ---------------- */
__global__ __launch_bounds__(256)
void split3_kernel(const float* __restrict__ x, unsigned short* __restrict__ hi,
                   unsigned short* __restrict__ md, unsigned short* __restrict__ lo,
                   float scale, size_t n)
{
    size_t i = (size_t)blockIdx.x * 256 + threadIdx.x;
    if (i < n) {
        float v = x[i] * scale;
        unsigned short h = f2bf(v);
        float r1 = v - bf2f(h);
        unsigned short m = f2bf(r1);
        float r2 = r1 - bf2f(m);
        hi[i] = h;
        md[i] = m;
        lo[i] = f2bf(r2);
    }
}

/* W[k][n] -> WT[n][k] 2-way */
__global__ __launch_bounds__(256)
void wtrans_split(const float* __restrict__ W, unsigned short* __restrict__ Thi,
                  unsigned short* __restrict__ Tlo)
{
    __shared__ float t[32][33];
    const int bx = blockIdx.x * 32;
    const int by = blockIdx.y * 32;
    const int tx = threadIdx.x;
    const int ty = threadIdx.y;
    for (int j = ty; j < 32; j += 8) {
        t[j][tx] = W[(size_t)(by + j) * DMODEL + bx + tx];
    }
    __syncthreads();
    for (int j = ty; j < 32; j += 8) {
        float v = t[tx][j];
        size_t o = (size_t)(bx + j) * DMODEL + by + tx;
        unsigned short h = f2bf(v);
        Thi[o] = h;
        Tlo[o] = f2bf(v - bf2f(h));
    }
}

/* W[k][n] -> WT[n][k] 3-way */
__global__ __launch_bounds__(256)
void wtrans_split3(const float* __restrict__ W, unsigned short* __restrict__ Thi,
                   unsigned short* __restrict__ Tmd, unsigned short* __restrict__ Tlo)
{
    __shared__ float t[32][33];
    const int bx = blockIdx.x * 32;
    const int by = blockIdx.y * 32;
    const int tx = threadIdx.x;
    const int ty = threadIdx.y;
    for (int j = ty; j < 32; j += 8) {
        t[j][tx] = W[(size_t)(by + j) * DMODEL + bx + tx];
    }
    __syncthreads();
    for (int j = ty; j < 32; j += 8) {
        float v = t[tx][j];
        size_t o = (size_t)(bx + j) * DMODEL + by + tx;
        unsigned short h = f2bf(v);
        float r1 = v - bf2f(h);
        unsigned short m = f2bf(r1);
        float r2 = r1 - bf2f(m);
        Thi[o] = h;
        Tmd[o] = m;
        Tlo[o] = f2bf(r2);
    }
}

/* V[tok][dmodel] -> Vt[bh][e][kseq] 2-way */
__global__ __launch_bounds__(256)
void vtrans_split(const float* __restrict__ V, unsigned short* __restrict__ Thi,
                  unsigned short* __restrict__ Tlo)
{
    __shared__ float t[32][33];
    const int bz = blockIdx.z;
    const int b = bz >> 4;
    const int h = bz & 15;
    const int k0 = blockIdx.x * 32;
    const int e0 = blockIdx.y * 32;
    const int tx = threadIdx.x;
    const int ty = threadIdx.y;
    for (int j = ty; j < 32; j += 8) {
        t[j][tx] = V[(size_t)(b * SEQ + k0 + j) * DMODEL + h * DKH + e0 + tx];
    }
    __syncthreads();
    for (int j = ty; j < 32; j += 8) {
        float v = t[tx][j];
        size_t o = (size_t)bz * DKH * SEQ + (size_t)(e0 + j) * SEQ + k0 + tx;
        unsigned short hv = f2bf(v);
        Thi[o] = hv;
        Tlo[o] = f2bf(v - bf2f(hv));
    }
}

/* ---------------- exact radix-select + masked softmax -> P hi/lo ------------- */
__device__ __forceinline__ unsigned int f2k(float f)
{
    unsigned int b = __float_as_uint(f);
    return (b & 0x80000000u) ? ~b : (b | 0x80000000u);
}

__global__ __launch_bounds__(256)
void topk_softmax_kernel(const float* __restrict__ S, unsigned short* __restrict__ Phi,
                         unsigned short* __restrict__ Plo)
{
    __shared__ float row[SEQ];
    __shared__ unsigned int hist[256];
    __shared__ float red[256];
    __shared__ unsigned int sh_prefix;
    __shared__ int sh_kk;

    const int tid = threadIdx.x;
    const float* Srow = S + (size_t)blockIdx.x * SEQ;
    unsigned short* PhiRow = Phi + (size_t)blockIdx.x * SEQ;
    unsigned short* PloRow = Plo + (size_t)blockIdx.x * SEQ;

    float m = -3.4e38f;
    #pragma unroll
    for (int i = 0; i < 8; i++) {
        float f = Srow[tid + i * 256];
        row[tid + i * 256] = f;
        m = fmaxf(m, f);
    }
    red[tid] = m;
    __syncthreads();
    for (int s = 128; s > 0; s >>= 1) {
        if (tid < s) red[tid] = fmaxf(red[tid], red[tid + s]);
        __syncthreads();
    }
    const float rowmax = red[0];
    __syncthreads();

    unsigned int prefix = 0;
    unsigned int prefmask = 0;
    int kk = TOPK;
    #pragma unroll
    for (int pass = 0; pass < 4; pass++) {
        const int shift = 24 - 8 * pass;
        hist[tid] = 0;
        __syncthreads();
        #pragma unroll
        for (int i = 0; i < 8; i++) {
            unsigned int key = f2k(row[tid + i * 256]);
            if ((key & prefmask) == prefix)
                atomicAdd(&hist[(key >> shift) & 255u], 1u);
        }
        __syncthreads();
        if (tid == 0) {
            int cum = 0;
            int d = 255;
            for (; d > 0; d--) {
                int c = (int)hist[d];
                if (cum + c >= kk) break;
                cum += c;
            }
            sh_prefix = prefix | ((unsigned int)d << shift);
            sh_kk = kk - cum;
        }
        __syncthreads();
        prefix = sh_prefix;
        kk = sh_kk;
        prefmask |= (0xFFu << shift);
        __syncthreads();
    }
    const unsigned int tkey = prefix;

    float lsum = 0.f;
    #pragma unroll
    for (int i = 0; i < 8; i++) {
        int idx = tid + i * 256;
        float f = row[idx];
        float p = (f2k(f) >= tkey) ? __expf(f - rowmax) : 0.f;
        row[idx] = p;
        lsum += p;
    }
    red[tid] = lsum;
    __syncthreads();
    for (int s = 128; s > 0; s >>= 1) {
        if (tid < s) red[tid] += red[tid + s];
        __syncthreads();
    }
    const float inv = 1.0f / red[0];
    #pragma unroll
    for (int i = 0; i < 8; i++) {
        int idx = tid + i * 256;
        float p = row[idx] * inv;
        unsigned short h = f2bf(p);
        PhiRow[idx] = h;
        PloRow[idx] = f2bf(p - bf2f(h));
    }
}

/* ============================ launch ============================ */
extern "C" void kernel_launch(void* const* d_in, const int* in_sizes, int n_in,
                              void* d_out, int out_size)
{
    (void)in_sizes; (void)n_in; (void)out_size;
    const float* queries = (const float*)d_in[0];
    const float* keys    = (const float*)d_in[1];
    const float* values  = (const float*)d_in[2];
    const float* Wq = (const float*)d_in[3];
    const float* bq = (const float*)d_in[4];
    const float* Wk = (const float*)d_in[5];
    const float* bk = (const float*)d_in[6];
    const float* Wv = (const float*)d_in[7];
    const float* bv = (const float*)d_in[8];
    const float* Wo = (const float*)d_in[9];
    const float* bo = (const float*)d_in[10];
    float* out = (float*)d_out;

    float* gf32 = 0;
    float* gS = 0;
    unsigned short* ginh = 0;
    unsigned short* ginm = 0;
    unsigned short* ginl = 0;
    unsigned short* gwth = 0;
    unsigned short* gwtm = 0;
    unsigned short* gwtl = 0;
    unsigned short* gqh = 0;
    unsigned short* gqm = 0;
    unsigned short* gql = 0;
    unsigned short* gkh = 0;
    unsigned short* gkm = 0;
    unsigned short* gkl = 0;
    unsigned short* gvth = 0;
    unsigned short* gvtl = 0;
    unsigned short* gph = 0;
    unsigned short* gpl = 0;
    cudaGetSymbolAddress((void**)&gf32, g_f32);
    cudaGetSymbolAddress((void**)&gS,   g_S);
    cudaGetSymbolAddress((void**)&ginh, g_inhi);
    cudaGetSymbolAddress((void**)&ginm, g_inmd);
    cudaGetSymbolAddress((void**)&ginl, g_inlo);
    cudaGetSymbolAddress((void**)&gwth, g_wthi);
    cudaGetSymbolAddress((void**)&gwtm, g_wtmd);
    cudaGetSymbolAddress((void**)&gwtl, g_wtlo);
    cudaGetSymbolAddress((void**)&gqh,  g_qhi);
    cudaGetSymbolAddress((void**)&gqm,  g_qmd);
    cudaGetSymbolAddress((void**)&gql,  g_qlo);
    cudaGetSymbolAddress((void**)&gkh,  g_khi);
    cudaGetSymbolAddress((void**)&gkm,  g_kmd);
    cudaGetSymbolAddress((void**)&gkl,  g_klo);
    cudaGetSymbolAddress((void**)&gvth, g_vthi);
    cudaGetSymbolAddress((void**)&gvtl, g_vtlo);
    cudaGetSymbolAddress((void**)&gph,  g_phi);
    cudaGetSymbolAddress((void**)&gpl,  g_plo);

    const size_t nTok = (size_t)NTOK * DMODEL;
    dim3 splitGrid((unsigned)((nTok + 255) / 256));
    dim3 wtGrid(32, 32);
    dim3 wtBlk(32, 8);
    dim3 projGrid(DMODEL / GBN, NTOK / GBM, 1);
    dim3 scoreGrid(SEQ / GBN, SEQ / GBM, NBH);
    dim3 avGrid(1, SEQ / GBM, NBH);
    dim3 vtGrid(SEQ / 32, DKH / 32, NBH);

    /* Q projection (3-way, 6-product) */
    split3_kernel<<<splitGrid, 256>>>(queries, ginh, ginm, ginl, 1.0f, nTok);
    wtrans_split3<<<wtGrid, wtBlk>>>(Wq, gwth, gwtm, gwtl);
    gemm_bf16x6_nt<<<projGrid, 128>>>(ginh, ginm, ginl, gwth, gwtm, gwtl, bq, gf32,
        DMODEL, DMODEL, DMODEL, DMODEL, 0LL, 0LL, 0LL, 0LL, 0LL, 0LL, 1);
    split3_kernel<<<splitGrid, 256>>>(gf32, gqh, gqm, gql, 0.125f, nTok);

    /* K projection (3-way, 6-product) */
    split3_kernel<<<splitGrid, 256>>>(keys, ginh, ginm, ginl, 1.0f, nTok);
    wtrans_split3<<<wtGrid, wtBlk>>>(Wk, gwth, gwtm, gwtl);
    gemm_bf16x6_nt<<<projGrid, 128>>>(ginh, ginm, ginl, gwth, gwtm, gwtl, bk, gf32,
        DMODEL, DMODEL, DMODEL, DMODEL, 0LL, 0LL, 0LL, 0LL, 0LL, 0LL, 1);
    split3_kernel<<<splitGrid, 256>>>(gf32, gkh, gkm, gkl, 1.0f, nTok);

    /* V projection (2-way, 4-product) + transpose */
    split_kernel<<<splitGrid, 256>>>(values, ginh, ginl, 1.0f, nTok);
    wtrans_split<<<wtGrid, wtBlk>>>(Wv, gwth, gwtl);
    gemm_bf16x4_nt<<<projGrid, 128>>>(ginh, ginl, gwth, gwtl, bv, gf32,
        DMODEL, DMODEL, DMODEL, DMODEL, 0LL, 0LL, 0LL, 0LL, 0LL, 0LL, 1);
    vtrans_split<<<vtGrid, wtBlk>>>(gf32, gvth, gvtl);

    /* scores: S[bh][q][k] = (Q/8) @ K^T (3-way, 6-product) */
    gemm_bf16x6_nt<<<scoreGrid, 128>>>(gqh, gqm, gql, gkh, gkm, gkl, (const float*)0, gS,
        DKH, DMODEL, DMODEL, SEQ,
        (long long)SEQ * DMODEL, (long long)DKH,
        (long long)SEQ * DMODEL, (long long)DKH,
        16LL * SEQ * SEQ, (long long)SEQ * SEQ, NHEADS);

    /* top-k + softmax -> P hi/lo */
    topk_softmax_kernel<<<NBH * SEQ, 256>>>(gS, gph, gpl);

    /* context = P @ V (2-way, 4-product; NT with Vt[bh][e][k]) */
    gemm_bf16x4_nt<<<avGrid, 128>>>(gph, gpl, gvth, gvtl, (const float*)0, gf32,
        SEQ, SEQ, SEQ, DMODEL,
        16LL * SEQ * SEQ, (long long)SEQ * SEQ,
        16LL * DKH * SEQ, (long long)DKH * SEQ,
        (long long)SEQ * DMODEL, (long long)DKH, NHEADS);

    /* output projection (2-way, 4-product) */
    split_kernel<<<splitGrid, 256>>>(gf32, ginh, ginl, 1.0f, nTok);
    wtrans_split<<<wtGrid, wtBlk>>>(Wo, gwth, gwtl);
    gemm_bf16x4_nt<<<projGrid, 128>>>(ginh, ginl, gwth, gwtl, bo, out,
        DMODEL, DMODEL, DMODEL, DMODEL, 0LL, 0LL, 0LL, 0LL, 0LL, 0LL, 1);
}

// round 12
// speedup vs baseline: 1.3022x; 1.1673x over previous
#include <cuda_runtime.h>

#define DMODEL 1024
#define NHEADS 16
#define DKH    64
#define BATCH  2
#define SEQ    2048
#define NTOK   (BATCH*SEQ)
#define NBH    (BATCH*NHEADS)
#define TOPK   512
#define LDSM   24

/* GEMM tile config (BM=128 BN=64, 4 warps 2x2) */
#define GBM 128
#define GBN 64
#define GWM 64
#define GWN 32
#define GMI 4
#define GNI 4
#define GNJ 2
#define GNA 2
#define GNB 1

/* fp16 stored as raw unsigned short (no cuda_fp16.h) */

/* ---------------- scratch (static device globals) ---------------- */
__device__ float g_f32[(size_t)NTOK * DMODEL];
__device__ float g_S[(size_t)NBH * SEQ * SEQ];
__device__ unsigned short g_inhi[(size_t)NTOK * DMODEL];
__device__ unsigned short g_inlo[(size_t)NTOK * DMODEL];
__device__ unsigned short g_wthi[(size_t)DMODEL * DMODEL];
__device__ unsigned short g_wtlo[(size_t)DMODEL * DMODEL];
__device__ unsigned short g_qhi[(size_t)NTOK * DMODEL];
__device__ unsigned short g_qlo[(size_t)NTOK * DMODEL];
__device__ unsigned short g_khi[(size_t)NTOK * DMODEL];
__device__ unsigned short g_klo[(size_t)NTOK * DMODEL];
__device__ unsigned short g_vthi[(size_t)NBH * DKH * SEQ];
__device__ unsigned short g_vtlo[(size_t)NBH * DKH * SEQ];
__device__ unsigned short g_phi[(size_t)NBH * SEQ * SEQ];
__device__ unsigned short g_plo[(size_t)NBH * SEQ * SEQ];

/* ---------------- fp16 conversion helpers (PTX, no headers) -------- */
__device__ __forceinline__ unsigned short f2h(float f)
{
    unsigned short h;
    asm("cvt.rn.f16.f32 %0, %1;" : "=h"(h) : "f"(f));
    return h;
}

__device__ __forceinline__ float h2f(unsigned short h)
{
    float f;
    asm("cvt.f32.f16 %0, %1;" : "=f"(f) : "h"(h));
    return f;
}

/* ---------------- mma / ldmatrix helpers ---------------- */
__device__ __forceinline__ void ldm4(unsigned int* r, const void* p)
{
    unsigned int a = (unsigned int)__cvta_generic_to_shared(p);
    asm volatile("ldmatrix.sync.aligned.m8n8.x4.shared.b16 {%0,%1,%2,%3},[%4];"
        : "=r"(r[0]), "=r"(r[1]), "=r"(r[2]), "=r"(r[3]) : "r"(a));
}

__device__ __forceinline__ void mma16816(float* d, const unsigned int* a,
                                         unsigned int b0, unsigned int b1)
{
    asm volatile("mma.sync.aligned.m16n8k16.row.col.f32.f16.f16.f32 "
        "{%0,%1,%2,%3},{%4,%5,%6,%7},{%8,%9},{%0,%1,%2,%3};"
        : "+f"(d[0]), "+f"(d[1]), "+f"(d[2]), "+f"(d[3])
        : "r"(a[0]), "r"(a[1]), "r"(a[2]), "r"(a[3]), "r"(b0), "r"(b1));
}

/* ============================================================================
   NT fp16x3 GEMM:  C[M,N-tile] = A[M,K] @ B[N,K]^T  (+ optional bias)
   2-way fp16 split (22 mantissa bits), 3 products: hh + hl + lh (ll ~2^-22
   dropped) -> fp32-class results at 3 mma per fragment pair.
   128x64 block, 4 warps (2x2), BK=16, double-buffered smem.
   Epilogue: if Chi != 0, write fused fp16 hi/lo split of (acc+bias)*cscale;
   else write fp32 (acc+bias)*cscale to C.
   Batched over blockIdx.z: (b,h) = (bz/HS, bz%HS).
   ========================================================================= */
__global__ __launch_bounds__(128)
void gemm_f16x3_nt(const unsigned short* __restrict__ Ahi,
                   const unsigned short* __restrict__ Alo,
                   const unsigned short* __restrict__ Bhi,
                   const unsigned short* __restrict__ Blo,
                   const float* __restrict__ bias, float* __restrict__ C,
                   unsigned short* __restrict__ Chi, unsigned short* __restrict__ Clo,
                   float cscale,
                   int K, int lda, int ldb, int ldc,
                   long long sAb, long long sAh, long long sBb, long long sBh,
                   long long sCb, long long sCh, int HS)
{
    __shared__ unsigned short sA[2][2][GBM][LDSM];
    __shared__ unsigned short sB[2][2][GBN][LDSM];

    const int tid  = threadIdx.x;
    const int warp = tid >> 5;
    const int lane = tid & 31;
    const int wm   = warp >> 1;
    const int wn   = warp & 1;
    const int bz   = blockIdx.z;
    const int bb   = bz / HS;
    const int hh   = bz % HS;

    const unsigned short* Ah = Ahi + (size_t)bb * sAb + (size_t)hh * sAh + (size_t)blockIdx.y * GBM * lda;
    const unsigned short* Al = Alo + (size_t)bb * sAb + (size_t)hh * sAh + (size_t)blockIdx.y * GBM * lda;
    const unsigned short* Bh = Bhi + (size_t)bb * sBb + (size_t)hh * sBh + (size_t)blockIdx.x * GBN * ldb;
    const unsigned short* Bl = Blo + (size_t)bb * sBb + (size_t)hh * sBh + (size_t)blockIdx.x * GBN * ldb;

    float acc[GMI][GNI][4];
    #pragma unroll
    for (int i = 0; i < GMI; i++) {
        #pragma unroll
        for (int j = 0; j < GNI; j++) {
            acc[i][j][0] = 0.f; acc[i][j][1] = 0.f;
            acc[i][j][2] = 0.f; acc[i][j][3] = 0.f;
        }
    }

    uint4 rah[GNA], ral[GNA], rbh[GNB], rbl[GNB];
    const int KT = K / 16;

    /* ---- prologue: load k-tile 0 into smem buffer 0 ---- */
    #pragma unroll
    for (int i = 0; i < GNA; i++) {
        int idx = tid + i * 128;
        int r = idx >> 1;
        int c = idx & 1;
        rah[i] = *(const uint4*)(Ah + (size_t)r * lda + c * 8);
        ral[i] = *(const uint4*)(Al + (size_t)r * lda + c * 8);
    }
    #pragma unroll
    for (int i = 0; i < GNB; i++) {
        int idx = tid + i * 128;
        int r = idx >> 1;
        int c = idx & 1;
        rbh[i] = *(const uint4*)(Bh + (size_t)r * ldb + c * 8);
        rbl[i] = *(const uint4*)(Bl + (size_t)r * ldb + c * 8);
    }
    #pragma unroll
    for (int i = 0; i < GNA; i++) {
        int idx = tid + i * 128;
        int r = idx >> 1;
        int c = idx & 1;
        *(uint4*)&sA[0][0][r][c * 8] = rah[i];
        *(uint4*)&sA[0][1][r][c * 8] = ral[i];
    }
    #pragma unroll
    for (int i = 0; i < GNB; i++) {
        int idx = tid + i * 128;
        int r = idx >> 1;
        int c = idx & 1;
        *(uint4*)&sB[0][0][r][c * 8] = rbh[i];
        *(uint4*)&sB[0][1][r][c * 8] = rbl[i];
    }
    __syncthreads();

    /* ---- mainloop ---- */
    for (int kt = 0; kt < KT; kt++) {
        int buf = kt & 1;
        int more = (kt + 1 < KT) ? 1 : 0;

        if (more) {
            int k0 = (kt + 1) * 16;
            #pragma unroll
            for (int i = 0; i < GNA; i++) {
                int idx = tid + i * 128;
                int r = idx >> 1;
                int c = idx & 1;
                rah[i] = *(const uint4*)(Ah + (size_t)r * lda + k0 + c * 8);
                ral[i] = *(const uint4*)(Al + (size_t)r * lda + k0 + c * 8);
            }
            #pragma unroll
            for (int i = 0; i < GNB; i++) {
                int idx = tid + i * 128;
                int r = idx >> 1;
                int c = idx & 1;
                rbh[i] = *(const uint4*)(Bh + (size_t)r * ldb + k0 + c * 8);
                rbl[i] = *(const uint4*)(Bl + (size_t)r * ldb + k0 + c * 8);
            }
        }

        {
            unsigned int fah[GMI][4], fal[GMI][4], fbh2[GNJ][4], fbl2[GNJ][4];
            #pragma unroll
            for (int mi = 0; mi < GMI; mi++) {
                ldm4(fah[mi], &sA[buf][0][wm * GWM + mi * 16 + (lane & 15)][(lane >> 4) * 8]);
                ldm4(fal[mi], &sA[buf][1][wm * GWM + mi * 16 + (lane & 15)][(lane >> 4) * 8]);
            }
            #pragma unroll
            for (int nj = 0; nj < GNJ; nj++) {
                ldm4(fbh2[nj], &sB[buf][0][wn * GWN + nj * 16 + (lane & 15)][(lane >> 4) * 8]);
                ldm4(fbl2[nj], &sB[buf][1][wn * GWN + nj * 16 + (lane & 15)][(lane >> 4) * 8]);
            }
            #pragma unroll
            for (int mi = 0; mi < GMI; mi++) {
                #pragma unroll
                for (int nj = 0; nj < GNJ; nj++) {
                    float* c0 = acc[mi][2 * nj];
                    float* c1 = acc[mi][2 * nj + 1];
                    /* hh + hl + lh (ll dropped, ~2^-22) */
                    mma16816(c0, fah[mi], fbh2[nj][0], fbh2[nj][2]);
                    mma16816(c0, fah[mi], fbl2[nj][0], fbl2[nj][2]);
                    mma16816(c0, fal[mi], fbh2[nj][0], fbh2[nj][2]);
                    mma16816(c1, fah[mi], fbh2[nj][1], fbh2[nj][3]);
                    mma16816(c1, fah[mi], fbl2[nj][1], fbl2[nj][3]);
                    mma16816(c1, fal[mi], fbh2[nj][1], fbh2[nj][3]);
                }
            }
        }

        if (more) {
            int nb = buf ^ 1;
            #pragma unroll
            for (int i = 0; i < GNA; i++) {
                int idx = tid + i * 128;
                int r = idx >> 1;
                int c = idx & 1;
                *(uint4*)&sA[nb][0][r][c * 8] = rah[i];
                *(uint4*)&sA[nb][1][r][c * 8] = ral[i];
            }
            #pragma unroll
            for (int i = 0; i < GNB; i++) {
                int idx = tid + i * 128;
                int r = idx >> 1;
                int c = idx & 1;
                *(uint4*)&sB[nb][0][r][c * 8] = rbh[i];
                *(uint4*)&sB[nb][1][r][c * 8] = rbl[i];
            }
        }
        __syncthreads();
    }

    /* ---- epilogue ---- */
    const int m0 = blockIdx.y * GBM + wm * GWM;
    const int n0 = blockIdx.x * GBN + wn * GWN;

    if (Chi) {
        unsigned short* Chp = Chi + (size_t)bb * sCb + (size_t)hh * sCh;
        unsigned short* Clp = Clo + (size_t)bb * sCb + (size_t)hh * sCh;
        #pragma unroll
        for (int mi = 0; mi < GMI; mi++) {
            #pragma unroll
            for (int ni = 0; ni < GNI; ni++) {
                int row = m0 + mi * 16 + (lane >> 2);
                int col = n0 + ni * 8 + (lane & 3) * 2;
                float b0 = 0.f;
                float b1 = 0.f;
                if (bias) {
                    b0 = bias[col];
                    b1 = bias[col + 1];
                }
                float v0 = (acc[mi][ni][0] + b0) * cscale;
                float v1 = (acc[mi][ni][1] + b1) * cscale;
                float v2 = (acc[mi][ni][2] + b0) * cscale;
                float v3 = (acc[mi][ni][3] + b1) * cscale;
                unsigned short h0 = f2h(v0);
                unsigned short h1 = f2h(v1);
                unsigned short h2 = f2h(v2);
                unsigned short h3 = f2h(v3);
                unsigned short l0 = f2h(v0 - h2f(h0));
                unsigned short l1 = f2h(v1 - h2f(h1));
                unsigned short l2 = f2h(v2 - h2f(h2));
                unsigned short l3 = f2h(v3 - h2f(h3));
                *(unsigned int*)(Chp + (size_t)row * ldc + col)       = (unsigned int)h0 | ((unsigned int)h1 << 16);
                *(unsigned int*)(Chp + (size_t)(row + 8) * ldc + col) = (unsigned int)h2 | ((unsigned int)h3 << 16);
                *(unsigned int*)(Clp + (size_t)row * ldc + col)       = (unsigned int)l0 | ((unsigned int)l1 << 16);
                *(unsigned int*)(Clp + (size_t)(row + 8) * ldc + col) = (unsigned int)l2 | ((unsigned int)l3 << 16);
            }
        }
    } else {
        float* Cp = C + (size_t)bb * sCb + (size_t)hh * sCh;
        #pragma unroll
        for (int mi = 0; mi < GMI; mi++) {
            #pragma unroll
            for (int ni = 0; ni < GNI; ni++) {
                int row = m0 + mi * 16 + (lane >> 2);
                int col = n0 + ni * 8 + (lane & 3) * 2;
                float b0 = 0.f;
                float b1 = 0.f;
                if (bias) {
                    b0 = bias[col];
                    b1 = bias[col + 1];
                }
                Cp[(size_t)row * ldc + col]           = (acc[mi][ni][0] + b0) * cscale;
                Cp[(size_t)row * ldc + col + 1]       = (acc[mi][ni][1] + b1) * cscale;
                Cp[(size_t)(row + 8) * ldc + col]     = (acc[mi][ni][2] + b0) * cscale;
                Cp[(size_t)(row + 8) * ldc + col + 1] = (acc[mi][ni][3] + b1) * cscale;
            }
        }
    }
}

/* ---------------- elementwise fp16 hi/lo split ---------------- */
__global__ __launch_bounds__(256)
void split_kernel(const float* __restrict__ x, unsigned short* __restrict__ hi,
                  unsigned short* __restrict__ lo, float scale, size_t n)
{
    size_t i = (size_t)blockIdx.x * 256 + threadIdx.x;
    if (i < n) {
        float v = x[i] * scale;
        unsigned short h = f2h(v);
        hi[i] = h;
        lo[i] = f2h(v - h2f(h));
    }
}

/* W[k][n] -> WT[n][k] fp16 hi/lo */
__global__ __launch_bounds__(256)
void wtrans_split(const float* __restrict__ W, unsigned short* __restrict__ Thi,
                  unsigned short* __restrict__ Tlo)
{
    __shared__ float t[32][33];
    const int bx = blockIdx.x * 32;
    const int by = blockIdx.y * 32;
    const int tx = threadIdx.x;
    const int ty = threadIdx.y;
    for (int j = ty; j < 32; j += 8) {
        t[j][tx] = W[(size_t)(by + j) * DMODEL + bx + tx];
    }
    __syncthreads();
    for (int j = ty; j < 32; j += 8) {
        float v = t[tx][j];
        size_t o = (size_t)(bx + j) * DMODEL + by + tx;
        unsigned short h = f2h(v);
        Thi[o] = h;
        Tlo[o] = f2h(v - h2f(h));
    }
}

/* V[tok][dmodel] -> Vt[bh][e][kseq] fp16 hi/lo */
__global__ __launch_bounds__(256)
void vtrans_split(const float* __restrict__ V, unsigned short* __restrict__ Thi,
                  unsigned short* __restrict__ Tlo)
{
    __shared__ float t[32][33];
    const int bz = blockIdx.z;
    const int b = bz >> 4;
    const int h = bz & 15;
    const int k0 = blockIdx.x * 32;
    const int e0 = blockIdx.y * 32;
    const int tx = threadIdx.x;
    const int ty = threadIdx.y;
    for (int j = ty; j < 32; j += 8) {
        t[j][tx] = V[(size_t)(b * SEQ + k0 + j) * DMODEL + h * DKH + e0 + tx];
    }
    __syncthreads();
    for (int j = ty; j < 32; j += 8) {
        float v = t[tx][j];
        size_t o = (size_t)bz * DKH * SEQ + (size_t)(e0 + j) * SEQ + k0 + tx;
        unsigned short hv = f2h(v);
        Thi[o] = hv;
        Tlo[o] = f2h(v - h2f(hv));
    }
}

/* ---------------- exact radix-select + masked softmax -> P hi/lo ------------- */
__device__ __forceinline__ unsigned int f2k(float f)
{
    unsigned int b = __float_as_uint(f);
    return (b & 0x80000000u) ? ~b : (b | 0x80000000u);
}

__global__ __launch_bounds__(256)
void topk_softmax_kernel(const float* __restrict__ S, unsigned short* __restrict__ Phi,
                         unsigned short* __restrict__ Plo)
{
    __shared__ float row[SEQ];
    __shared__ unsigned int hist[256];
    __shared__ float red[256];
    __shared__ unsigned int sh_prefix;
    __shared__ int sh_kk;

    const int tid = threadIdx.x;
    const float* Srow = S + (size_t)blockIdx.x * SEQ;
    unsigned short* PhiRow = Phi + (size_t)blockIdx.x * SEQ;
    unsigned short* PloRow = Plo + (size_t)blockIdx.x * SEQ;

    float m = -3.4e38f;
    #pragma unroll
    for (int i = 0; i < 8; i++) {
        float f = Srow[tid + i * 256];
        row[tid + i * 256] = f;
        m = fmaxf(m, f);
    }
    red[tid] = m;
    __syncthreads();
    for (int s = 128; s > 0; s >>= 1) {
        if (tid < s) red[tid] = fmaxf(red[tid], red[tid + s]);
        __syncthreads();
    }
    const float rowmax = red[0];
    __syncthreads();

    unsigned int prefix = 0;
    unsigned int prefmask = 0;
    int kk = TOPK;
    #pragma unroll
    for (int pass = 0; pass < 4; pass++) {
        const int shift = 24 - 8 * pass;
        hist[tid] = 0;
        __syncthreads();
        #pragma unroll
        for (int i = 0; i < 8; i++) {
            unsigned int key = f2k(row[tid + i * 256]);
            if ((key & prefmask) == prefix)
                atomicAdd(&hist[(key >> shift) & 255u], 1u);
        }
        __syncthreads();
        if (tid == 0) {
            int cum = 0;
            int d = 255;
            for (; d > 0; d--) {
                int c = (int)hist[d];
                if (cum + c >= kk) break;
                cum += c;
            }
            sh_prefix = prefix | ((unsigned int)d << shift);
            sh_kk = kk - cum;
        }
        __syncthreads();
        prefix = sh_prefix;
        kk = sh_kk;
        prefmask |= (0xFFu << shift);
        __syncthreads();
    }
    const unsigned int tkey = prefix;

    float lsum = 0.f;
    #pragma unroll
    for (int i = 0; i < 8; i++) {
        int idx = tid + i * 256;
        float f = row[idx];
        float p = (f2k(f) >= tkey) ? __expf(f - rowmax) : 0.f;
        row[idx] = p;
        lsum += p;
    }
    red[tid] = lsum;
    __syncthreads();
    for (int s = 128; s > 0; s >>= 1) {
        if (tid < s) red[tid] += red[tid + s];
        __syncthreads();
    }
    const float inv = 1.0f / red[0];
    #pragma unroll
    for (int i = 0; i < 8; i++) {
        int idx = tid + i * 256;
        float p = row[idx] * inv;
        unsigned short h = f2h(p);
        PhiRow[idx] = h;
        PloRow[idx] = f2h(p - h2f(h));
    }
}

/* ============================ launch ============================ */
extern "C" void kernel_launch(void* const* d_in, const int* in_sizes, int n_in,
                              void* d_out, int out_size)
{
    (void)in_sizes; (void)n_in; (void)out_size;
    const float* queries = (const float*)d_in[0];
    const float* keys    = (const float*)d_in[1];
    const float* values  = (const float*)d_in[2];
    const float* Wq = (const float*)d_in[3];
    const float* bq = (const float*)d_in[4];
    const float* Wk = (const float*)d_in[5];
    const float* bk = (const float*)d_in[6];
    const float* Wv = (const float*)d_in[7];
    const float* bv = (const float*)d_in[8];
    const float* Wo = (const float*)d_in[9];
    const float* bo = (const float*)d_in[10];
    float* out = (float*)d_out;

    float* gf32 = 0;
    float* gS = 0;
    unsigned short* ginh = 0;
    unsigned short* ginl = 0;
    unsigned short* gwth = 0;
    unsigned short* gwtl = 0;
    unsigned short* gqh = 0;
    unsigned short* gql = 0;
    unsigned short* gkh = 0;
    unsigned short* gkl = 0;
    unsigned short* gvth = 0;
    unsigned short* gvtl = 0;
    unsigned short* gph = 0;
    unsigned short* gpl = 0;
    cudaGetSymbolAddress((void**)&gf32, g_f32);
    cudaGetSymbolAddress((void**)&gS,   g_S);
    cudaGetSymbolAddress((void**)&ginh, g_inhi);
    cudaGetSymbolAddress((void**)&ginl, g_inlo);
    cudaGetSymbolAddress((void**)&gwth, g_wthi);
    cudaGetSymbolAddress((void**)&gwtl, g_wtlo);
    cudaGetSymbolAddress((void**)&gqh,  g_qhi);
    cudaGetSymbolAddress((void**)&gql,  g_qlo);
    cudaGetSymbolAddress((void**)&gkh,  g_khi);
    cudaGetSymbolAddress((void**)&gkl,  g_klo);
    cudaGetSymbolAddress((void**)&gvth, g_vthi);
    cudaGetSymbolAddress((void**)&gvtl, g_vtlo);
    cudaGetSymbolAddress((void**)&gph,  g_phi);
    cudaGetSymbolAddress((void**)&gpl,  g_plo);

    const size_t nTok = (size_t)NTOK * DMODEL;
    dim3 splitGrid((unsigned)((nTok + 255) / 256));
    dim3 wtGrid(32, 32);
    dim3 wtBlk(32, 8);
    dim3 projGrid(DMODEL / GBN, NTOK / GBM, 1);
    dim3 scoreGrid(SEQ / GBN, SEQ / GBM, NBH);
    dim3 avGrid(1, SEQ / GBM, NBH);
    dim3 vtGrid(SEQ / 32, DKH / 32, NBH);

    /* Q projection: fused split epilogue, exact 1/8 scale folded in */
    split_kernel<<<splitGrid, 256>>>(queries, ginh, ginl, 1.0f, nTok);
    wtrans_split<<<wtGrid, wtBlk>>>(Wq, gwth, gwtl);
    gemm_f16x3_nt<<<projGrid, 128>>>(ginh, ginl, gwth, gwtl, bq, (float*)0, gqh, gql, 0.125f,
        DMODEL, DMODEL, DMODEL, DMODEL, 0LL, 0LL, 0LL, 0LL, 0LL, 0LL, 1);

    /* K projection: fused split epilogue */
    split_kernel<<<splitGrid, 256>>>(keys, ginh, ginl, 1.0f, nTok);
    wtrans_split<<<wtGrid, wtBlk>>>(Wk, gwth, gwtl);
    gemm_f16x3_nt<<<projGrid, 128>>>(ginh, ginl, gwth, gwtl, bk, (float*)0, gkh, gkl, 1.0f,
        DMODEL, DMODEL, DMODEL, DMODEL, 0LL, 0LL, 0LL, 0LL, 0LL, 0LL, 1);

    /* V projection (fp32 out) + per-head transpose split */
    split_kernel<<<splitGrid, 256>>>(values, ginh, ginl, 1.0f, nTok);
    wtrans_split<<<wtGrid, wtBlk>>>(Wv, gwth, gwtl);
    gemm_f16x3_nt<<<projGrid, 128>>>(ginh, ginl, gwth, gwtl, bv, gf32,
        (unsigned short*)0, (unsigned short*)0, 1.0f,
        DMODEL, DMODEL, DMODEL, DMODEL, 0LL, 0LL, 0LL, 0LL, 0LL, 0LL, 1);
    vtrans_split<<<vtGrid, wtBlk>>>(gf32, gvth, gvtl);

    /* scores: S[bh][q][k] = (Q/8) @ K^T (fp32 out) */
    gemm_f16x3_nt<<<scoreGrid, 128>>>(gqh, gql, gkh, gkl, (const float*)0, gS,
        (unsigned short*)0, (unsigned short*)0, 1.0f,
        DKH, DMODEL, DMODEL, SEQ,
        (long long)SEQ * DMODEL, (long long)DKH,
        (long long)SEQ * DMODEL, (long long)DKH,
        16LL * SEQ * SEQ, (long long)SEQ * SEQ, NHEADS);

    /* top-k + softmax -> P hi/lo */
    topk_softmax_kernel<<<NBH * SEQ, 256>>>(gS, gph, gpl);

    /* context = P @ V: fused split epilogue -> ctx hi/lo (reuse g_in buffers) */
    gemm_f16x3_nt<<<avGrid, 128>>>(gph, gpl, gvth, gvtl, (const float*)0, (float*)0,
        ginh, ginl, 1.0f,
        SEQ, SEQ, SEQ, DMODEL,
        16LL * SEQ * SEQ, (long long)SEQ * SEQ,
        16LL * DKH * SEQ, (long long)DKH * SEQ,
        (long long)SEQ * DMODEL, (long long)DKH, NHEADS);

    /* output projection (fp32 out) */
    wtrans_split<<<wtGrid, wtBlk>>>(Wo, gwth, gwtl);
    gemm_f16x3_nt<<<projGrid, 128>>>(ginh, ginl, gwth, gwtl, bo, out,
        (unsigned short*)0, (unsigned short*)0, 1.0f,
        DMODEL, DMODEL, DMODEL, DMODEL, 0LL, 0LL, 0LL, 0LL, 0LL, 0LL, 1);
}

// round 13
// speedup vs baseline: 1.6685x; 1.2813x over previous
#include <cuda_runtime.h>

#define DMODEL 1024
#define NHEADS 16
#define DKH    64
#define BATCH  2
#define SEQ    2048
#define NTOK   (BATCH*SEQ)
#define NBH    (BATCH*NHEADS)
#define TOPK   512
#define LDSM   24

/* GEMM tile config (BM=128 BN=64, 4 warps 2x2) */
#define GBM 128
#define GBN 64
#define GWM 64
#define GWN 32
#define GMI 4
#define GNI 4
#define GNJ 2
#define GNA 2
#define GNB 1

/* fp16 stored as raw unsigned short (no cuda_fp16.h) */

/* ---------------- scratch (static device globals) ---------------- */
__device__ float g_f32[(size_t)NTOK * DMODEL];
__device__ float g_S[(size_t)NBH * SEQ * SEQ];   /* also reused as split-K partial buffer */
__device__ unsigned short g_inhi[(size_t)NTOK * DMODEL];
__device__ unsigned short g_inlo[(size_t)NTOK * DMODEL];
__device__ unsigned short g_wthi[(size_t)DMODEL * DMODEL];
__device__ unsigned short g_wtlo[(size_t)DMODEL * DMODEL];
__device__ unsigned short g_qhi[(size_t)NTOK * DMODEL];
__device__ unsigned short g_qlo[(size_t)NTOK * DMODEL];
__device__ unsigned short g_khi[(size_t)NTOK * DMODEL];
__device__ unsigned short g_klo[(size_t)NTOK * DMODEL];
__device__ unsigned short g_vthi[(size_t)NBH * DKH * SEQ];
__device__ unsigned short g_vtlo[(size_t)NBH * DKH * SEQ];
__device__ unsigned short g_phi[(size_t)NBH * SEQ * SEQ];
__device__ unsigned short g_plo[(size_t)NBH * SEQ * SEQ];

/* ---------------- fp16 conversion helpers (PTX, no headers) -------- */
__device__ __forceinline__ unsigned short f2h(float f)
{
    unsigned short h;
    asm("cvt.rn.f16.f32 %0, %1;" : "=h"(h) : "f"(f));
    return h;
}

__device__ __forceinline__ float h2f(unsigned short h)
{
    float f;
    asm("cvt.f32.f16 %0, %1;" : "=f"(f) : "h"(h));
    return f;
}

/* ---------------- mma / ldmatrix helpers ---------------- */
__device__ __forceinline__ void ldm4(unsigned int* r, const void* p)
{
    unsigned int a = (unsigned int)__cvta_generic_to_shared(p);
    asm volatile("ldmatrix.sync.aligned.m8n8.x4.shared.b16 {%0,%1,%2,%3},[%4];"
        : "=r"(r[0]), "=r"(r[1]), "=r"(r[2]), "=r"(r[3]) : "r"(a));
}

__device__ __forceinline__ void mma16816(float* d, const unsigned int* a,
                                         unsigned int b0, unsigned int b1)
{
    asm volatile("mma.sync.aligned.m16n8k16.row.col.f32.f16.f16.f32 "
        "{%0,%1,%2,%3},{%4,%5,%6,%7},{%8,%9},{%0,%1,%2,%3};"
        : "+f"(d[0]), "+f"(d[1]), "+f"(d[2]), "+f"(d[3])
        : "r"(a[0]), "r"(a[1]), "r"(a[2]), "r"(a[3]), "r"(b0), "r"(b1));
}

/* ============================================================================
   NT fp16x3 GEMM:  C[M,N-tile] = A[M,K] @ B[N,K]^T
   2-way fp16 split (22 mantissa bits), 3 products: hh + hl + lh.
   128x64 block, 4 warps (2x2), BK=16, double-buffered smem.
   Split-K: blockIdx.z = bz*KS + ks; each ks handles K/KS contiguous k's.
     KS>1 : write raw fp32 partial to Cpart + ks*partStride (no bias/scale).
     KS=1 : epilogue writes either fused fp16 hi/lo split of (acc+bias)*cscale
            (Chi != 0) or fp32 (acc+bias)*cscale to C.
   ========================================================================= */
__global__ __launch_bounds__(128)
void gemm_f16x3_nt(const unsigned short* __restrict__ Ahi,
                   const unsigned short* __restrict__ Alo,
                   const unsigned short* __restrict__ Bhi,
                   const unsigned short* __restrict__ Blo,
                   const float* __restrict__ bias, float* __restrict__ C,
                   unsigned short* __restrict__ Chi, unsigned short* __restrict__ Clo,
                   float cscale,
                   int K, int lda, int ldb, int ldc,
                   long long sAb, long long sAh, long long sBb, long long sBh,
                   long long sCb, long long sCh, int HS,
                   float* __restrict__ Cpart, long long partStride, int KS)
{
    __shared__ unsigned short sA[2][2][GBM][LDSM];
    __shared__ unsigned short sB[2][2][GBN][LDSM];

    const int tid  = threadIdx.x;
    const int warp = tid >> 5;
    const int lane = tid & 31;
    const int wm   = warp >> 1;
    const int wn   = warp & 1;
    const int bzz  = blockIdx.z;
    const int ks   = bzz % KS;
    const int bz   = bzz / KS;
    const int bb   = bz / HS;
    const int hh   = bz % HS;
    const int kLen = K / KS;
    const int kOff = ks * kLen;

    const unsigned short* Ah = Ahi + (size_t)bb * sAb + (size_t)hh * sAh + (size_t)blockIdx.y * GBM * lda + kOff;
    const unsigned short* Al = Alo + (size_t)bb * sAb + (size_t)hh * sAh + (size_t)blockIdx.y * GBM * lda + kOff;
    const unsigned short* Bh = Bhi + (size_t)bb * sBb + (size_t)hh * sBh + (size_t)blockIdx.x * GBN * ldb + kOff;
    const unsigned short* Bl = Blo + (size_t)bb * sBb + (size_t)hh * sBh + (size_t)blockIdx.x * GBN * ldb + kOff;

    float acc[GMI][GNI][4];
    #pragma unroll
    for (int i = 0; i < GMI; i++) {
        #pragma unroll
        for (int j = 0; j < GNI; j++) {
            acc[i][j][0] = 0.f; acc[i][j][1] = 0.f;
            acc[i][j][2] = 0.f; acc[i][j][3] = 0.f;
        }
    }

    uint4 rah[GNA], ral[GNA], rbh[GNB], rbl[GNB];
    const int KT = kLen / 16;

    /* ---- prologue: load k-tile 0 into smem buffer 0 ---- */
    #pragma unroll
    for (int i = 0; i < GNA; i++) {
        int idx = tid + i * 128;
        int r = idx >> 1;
        int c = idx & 1;
        rah[i] = *(const uint4*)(Ah + (size_t)r * lda + c * 8);
        ral[i] = *(const uint4*)(Al + (size_t)r * lda + c * 8);
    }
    #pragma unroll
    for (int i = 0; i < GNB; i++) {
        int idx = tid + i * 128;
        int r = idx >> 1;
        int c = idx & 1;
        rbh[i] = *(const uint4*)(Bh + (size_t)r * ldb + c * 8);
        rbl[i] = *(const uint4*)(Bl + (size_t)r * ldb + c * 8);
    }
    #pragma unroll
    for (int i = 0; i < GNA; i++) {
        int idx = tid + i * 128;
        int r = idx >> 1;
        int c = idx & 1;
        *(uint4*)&sA[0][0][r][c * 8] = rah[i];
        *(uint4*)&sA[0][1][r][c * 8] = ral[i];
    }
    #pragma unroll
    for (int i = 0; i < GNB; i++) {
        int idx = tid + i * 128;
        int r = idx >> 1;
        int c = idx & 1;
        *(uint4*)&sB[0][0][r][c * 8] = rbh[i];
        *(uint4*)&sB[0][1][r][c * 8] = rbl[i];
    }
    __syncthreads();

    /* ---- mainloop ---- */
    for (int kt = 0; kt < KT; kt++) {
        int buf = kt & 1;
        int more = (kt + 1 < KT) ? 1 : 0;

        if (more) {
            int k0 = (kt + 1) * 16;
            #pragma unroll
            for (int i = 0; i < GNA; i++) {
                int idx = tid + i * 128;
                int r = idx >> 1;
                int c = idx & 1;
                rah[i] = *(const uint4*)(Ah + (size_t)r * lda + k0 + c * 8);
                ral[i] = *(const uint4*)(Al + (size_t)r * lda + k0 + c * 8);
            }
            #pragma unroll
            for (int i = 0; i < GNB; i++) {
                int idx = tid + i * 128;
                int r = idx >> 1;
                int c = idx & 1;
                rbh[i] = *(const uint4*)(Bh + (size_t)r * ldb + k0 + c * 8);
                rbl[i] = *(const uint4*)(Bl + (size_t)r * ldb + k0 + c * 8);
            }
        }

        {
            unsigned int fah[GMI][4], fal[GMI][4], fbh2[GNJ][4], fbl2[GNJ][4];
            #pragma unroll
            for (int mi = 0; mi < GMI; mi++) {
                ldm4(fah[mi], &sA[buf][0][wm * GWM + mi * 16 + (lane & 15)][(lane >> 4) * 8]);
                ldm4(fal[mi], &sA[buf][1][wm * GWM + mi * 16 + (lane & 15)][(lane >> 4) * 8]);
            }
            #pragma unroll
            for (int nj = 0; nj < GNJ; nj++) {
                ldm4(fbh2[nj], &sB[buf][0][wn * GWN + nj * 16 + (lane & 15)][(lane >> 4) * 8]);
                ldm4(fbl2[nj], &sB[buf][1][wn * GWN + nj * 16 + (lane & 15)][(lane >> 4) * 8]);
            }
            #pragma unroll
            for (int mi = 0; mi < GMI; mi++) {
                #pragma unroll
                for (int nj = 0; nj < GNJ; nj++) {
                    float* c0 = acc[mi][2 * nj];
                    float* c1 = acc[mi][2 * nj + 1];
                    mma16816(c0, fah[mi], fbh2[nj][0], fbh2[nj][2]);
                    mma16816(c0, fah[mi], fbl2[nj][0], fbl2[nj][2]);
                    mma16816(c0, fal[mi], fbh2[nj][0], fbh2[nj][2]);
                    mma16816(c1, fah[mi], fbh2[nj][1], fbh2[nj][3]);
                    mma16816(c1, fah[mi], fbl2[nj][1], fbl2[nj][3]);
                    mma16816(c1, fal[mi], fbh2[nj][1], fbh2[nj][3]);
                }
            }
        }

        if (more) {
            int nb = buf ^ 1;
            #pragma unroll
            for (int i = 0; i < GNA; i++) {
                int idx = tid + i * 128;
                int r = idx >> 1;
                int c = idx & 1;
                *(uint4*)&sA[nb][0][r][c * 8] = rah[i];
                *(uint4*)&sA[nb][1][r][c * 8] = ral[i];
            }
            #pragma unroll
            for (int i = 0; i < GNB; i++) {
                int idx = tid + i * 128;
                int r = idx >> 1;
                int c = idx & 1;
                *(uint4*)&sB[nb][0][r][c * 8] = rbh[i];
                *(uint4*)&sB[nb][1][r][c * 8] = rbl[i];
            }
        }
        __syncthreads();
    }

    /* ---- epilogue ---- */
    const int m0 = blockIdx.y * GBM + wm * GWM;
    const int n0 = blockIdx.x * GBN + wn * GWN;

    if (KS > 1) {
        float* Pp = Cpart + (size_t)ks * partStride + (size_t)bb * sCb + (size_t)hh * sCh;
        #pragma unroll
        for (int mi = 0; mi < GMI; mi++) {
            #pragma unroll
            for (int ni = 0; ni < GNI; ni++) {
                int row = m0 + mi * 16 + (lane >> 2);
                int col = n0 + ni * 8 + (lane & 3) * 2;
                Pp[(size_t)row * ldc + col]           = acc[mi][ni][0];
                Pp[(size_t)row * ldc + col + 1]       = acc[mi][ni][1];
                Pp[(size_t)(row + 8) * ldc + col]     = acc[mi][ni][2];
                Pp[(size_t)(row + 8) * ldc + col + 1] = acc[mi][ni][3];
            }
        }
    } else if (Chi) {
        unsigned short* Chp = Chi + (size_t)bb * sCb + (size_t)hh * sCh;
        unsigned short* Clp = Clo + (size_t)bb * sCb + (size_t)hh * sCh;
        #pragma unroll
        for (int mi = 0; mi < GMI; mi++) {
            #pragma unroll
            for (int ni = 0; ni < GNI; ni++) {
                int row = m0 + mi * 16 + (lane >> 2);
                int col = n0 + ni * 8 + (lane & 3) * 2;
                float b0 = 0.f;
                float b1 = 0.f;
                if (bias) {
                    b0 = bias[col];
                    b1 = bias[col + 1];
                }
                float v0 = (acc[mi][ni][0] + b0) * cscale;
                float v1 = (acc[mi][ni][1] + b1) * cscale;
                float v2 = (acc[mi][ni][2] + b0) * cscale;
                float v3 = (acc[mi][ni][3] + b1) * cscale;
                unsigned short h0 = f2h(v0);
                unsigned short h1 = f2h(v1);
                unsigned short h2 = f2h(v2);
                unsigned short h3 = f2h(v3);
                unsigned short l0 = f2h(v0 - h2f(h0));
                unsigned short l1 = f2h(v1 - h2f(h1));
                unsigned short l2 = f2h(v2 - h2f(h2));
                unsigned short l3 = f2h(v3 - h2f(h3));
                *(unsigned int*)(Chp + (size_t)row * ldc + col)       = (unsigned int)h0 | ((unsigned int)h1 << 16);
                *(unsigned int*)(Chp + (size_t)(row + 8) * ldc + col) = (unsigned int)h2 | ((unsigned int)h3 << 16);
                *(unsigned int*)(Clp + (size_t)row * ldc + col)       = (unsigned int)l0 | ((unsigned int)l1 << 16);
                *(unsigned int*)(Clp + (size_t)(row + 8) * ldc + col) = (unsigned int)l2 | ((unsigned int)l3 << 16);
            }
        }
    } else {
        float* Cp = C + (size_t)bb * sCb + (size_t)hh * sCh;
        #pragma unroll
        for (int mi = 0; mi < GMI; mi++) {
            #pragma unroll
            for (int ni = 0; ni < GNI; ni++) {
                int row = m0 + mi * 16 + (lane >> 2);
                int col = n0 + ni * 8 + (lane & 3) * 2;
                float b0 = 0.f;
                float b1 = 0.f;
                if (bias) {
                    b0 = bias[col];
                    b1 = bias[col + 1];
                }
                Cp[(size_t)row * ldc + col]           = (acc[mi][ni][0] + b0) * cscale;
                Cp[(size_t)row * ldc + col + 1]       = (acc[mi][ni][1] + b1) * cscale;
                Cp[(size_t)(row + 8) * ldc + col]     = (acc[mi][ni][2] + b0) * cscale;
                Cp[(size_t)(row + 8) * ldc + col + 1] = (acc[mi][ni][3] + b1) * cscale;
            }
        }
    }
}

/* ---------------- split-K combine: sum partials + bias + scale, write ------ */
__global__ __launch_bounds__(256)
void combine_kernel(const float* __restrict__ part, long long stride, int KS,
                    const float* __restrict__ bias, int biasMod, float scale,
                    float* __restrict__ outF,
                    unsigned short* __restrict__ outHi, unsigned short* __restrict__ outLo,
                    size_t n)
{
    size_t i = (size_t)blockIdx.x * 256 + threadIdx.x;
    if (i < n) {
        float s = part[i];
        for (int ks = 1; ks < KS; ks++)
            s += part[(size_t)ks * stride + i];
        if (bias) s += bias[i & (size_t)(biasMod - 1)];
        s *= scale;
        if (outHi) {
            unsigned short h = f2h(s);
            outHi[i] = h;
            outLo[i] = f2h(s - h2f(h));
        } else {
            outF[i] = s;
        }
    }
}

/* ---------------- elementwise fp16 hi/lo split ---------------- */
__global__ __launch_bounds__(256)
void split_kernel(const float* __restrict__ x, unsigned short* __restrict__ hi,
                  unsigned short* __restrict__ lo, float scale, size_t n)
{
    size_t i = (size_t)blockIdx.x * 256 + threadIdx.x;
    if (i < n) {
        float v = x[i] * scale;
        unsigned short h = f2h(v);
        hi[i] = h;
        lo[i] = f2h(v - h2f(h));
    }
}

/* W[k][n] -> WT[n][k] fp16 hi/lo */
__global__ __launch_bounds__(256)
void wtrans_split(const float* __restrict__ W, unsigned short* __restrict__ Thi,
                  unsigned short* __restrict__ Tlo)
{
    __shared__ float t[32][33];
    const int bx = blockIdx.x * 32;
    const int by = blockIdx.y * 32;
    const int tx = threadIdx.x;
    const int ty = threadIdx.y;
    for (int j = ty; j < 32; j += 8) {
        t[j][tx] = W[(size_t)(by + j) * DMODEL + bx + tx];
    }
    __syncthreads();
    for (int j = ty; j < 32; j += 8) {
        float v = t[tx][j];
        size_t o = (size_t)(bx + j) * DMODEL + by + tx;
        unsigned short h = f2h(v);
        Thi[o] = h;
        Tlo[o] = f2h(v - h2f(h));
    }
}

/* V[tok][dmodel] -> Vt[bh][e][kseq] fp16 hi/lo */
__global__ __launch_bounds__(256)
void vtrans_split(const float* __restrict__ V, unsigned short* __restrict__ Thi,
                  unsigned short* __restrict__ Tlo)
{
    __shared__ float t[32][33];
    const int bz = blockIdx.z;
    const int b = bz >> 4;
    const int h = bz & 15;
    const int k0 = blockIdx.x * 32;
    const int e0 = blockIdx.y * 32;
    const int tx = threadIdx.x;
    const int ty = threadIdx.y;
    for (int j = ty; j < 32; j += 8) {
        t[j][tx] = V[(size_t)(b * SEQ + k0 + j) * DMODEL + h * DKH + e0 + tx];
    }
    __syncthreads();
    for (int j = ty; j < 32; j += 8) {
        float v = t[tx][j];
        size_t o = (size_t)bz * DKH * SEQ + (size_t)(e0 + j) * SEQ + k0 + tx;
        unsigned short hv = f2h(v);
        Thi[o] = hv;
        Tlo[o] = f2h(v - h2f(hv));
    }
}

/* ---------------- exact radix-select + masked softmax -> P hi/lo ------------- */
__device__ __forceinline__ unsigned int f2k(float f)
{
    unsigned int b = __float_as_uint(f);
    return (b & 0x80000000u) ? ~b : (b | 0x80000000u);
}

__global__ __launch_bounds__(256)
void topk_softmax_kernel(const float* __restrict__ S, unsigned short* __restrict__ Phi,
                         unsigned short* __restrict__ Plo)
{
    __shared__ float row[SEQ];
    __shared__ unsigned int hist[256];
    __shared__ float red[256];
    __shared__ unsigned int sh_prefix;
    __shared__ int sh_kk;

    const int tid = threadIdx.x;
    const float* Srow = S + (size_t)blockIdx.x * SEQ;
    unsigned short* PhiRow = Phi + (size_t)blockIdx.x * SEQ;
    unsigned short* PloRow = Plo + (size_t)blockIdx.x * SEQ;

    float m = -3.4e38f;
    #pragma unroll
    for (int i = 0; i < 8; i++) {
        float f = Srow[tid + i * 256];
        row[tid + i * 256] = f;
        m = fmaxf(m, f);
    }
    red[tid] = m;
    __syncthreads();
    for (int s = 128; s > 0; s >>= 1) {
        if (tid < s) red[tid] = fmaxf(red[tid], red[tid + s]);
        __syncthreads();
    }
    const float rowmax = red[0];
    __syncthreads();

    unsigned int prefix = 0;
    unsigned int prefmask = 0;
    int kk = TOPK;
    #pragma unroll
    for (int pass = 0; pass < 4; pass++) {
        const int shift = 24 - 8 * pass;
        hist[tid] = 0;
        __syncthreads();
        #pragma unroll
        for (int i = 0; i < 8; i++) {
            unsigned int key = f2k(row[tid + i * 256]);
            if ((key & prefmask) == prefix)
                atomicAdd(&hist[(key >> shift) & 255u], 1u);
        }
        __syncthreads();

        /* parallel suffix-sum: hist[d] := count of candidate keys with bin >= d */
        unsigned int v = hist[tid];
        #pragma unroll
        for (int s = 1; s < 256; s <<= 1) {
            unsigned int add = (tid + s < 256) ? hist[tid + s] : 0u;
            __syncthreads();
            v += add;
            hist[tid] = v;
            __syncthreads();
        }
        unsigned int Cd  = hist[tid];
        unsigned int Cd1 = (tid < 255) ? hist[tid + 1] : 0u;
        if (Cd >= (unsigned int)kk && (tid == 255 || Cd1 < (unsigned int)kk)) {
            sh_prefix = prefix | ((unsigned int)tid << shift);
            sh_kk = kk - (int)Cd1;
        }
        __syncthreads();
        prefix = sh_prefix;
        kk = sh_kk;
        prefmask |= (0xFFu << shift);
        __syncthreads();
    }
    const unsigned int tkey = prefix;

    float lsum = 0.f;
    #pragma unroll
    for (int i = 0; i < 8; i++) {
        int idx = tid + i * 256;
        float f = row[idx];
        float p = (f2k(f) >= tkey) ? __expf(f - rowmax) : 0.f;
        row[idx] = p;
        lsum += p;
    }
    red[tid] = lsum;
    __syncthreads();
    for (int s = 128; s > 0; s >>= 1) {
        if (tid < s) red[tid] += red[tid + s];
        __syncthreads();
    }
    const float inv = 1.0f / red[0];
    #pragma unroll
    for (int i = 0; i < 8; i++) {
        int idx = tid + i * 256;
        float p = row[idx] * inv;
        unsigned short h = f2h(p);
        PhiRow[idx] = h;
        PloRow[idx] = f2h(p - h2f(h));
    }
}

/* ============================ launch ============================ */
extern "C" void kernel_launch(void* const* d_in, const int* in_sizes, int n_in,
                              void* d_out, int out_size)
{
    (void)in_sizes; (void)n_in; (void)out_size;
    const float* queries = (const float*)d_in[0];
    const float* keys    = (const float*)d_in[1];
    const float* values  = (const float*)d_in[2];
    const float* Wq = (const float*)d_in[3];
    const float* bq = (const float*)d_in[4];
    const float* Wk = (const float*)d_in[5];
    const float* bk = (const float*)d_in[6];
    const float* Wv = (const float*)d_in[7];
    const float* bv = (const float*)d_in[8];
    const float* Wo = (const float*)d_in[9];
    const float* bo = (const float*)d_in[10];
    float* out = (float*)d_out;

    float* gf32 = 0;
    float* gS = 0;
    unsigned short* ginh = 0;
    unsigned short* ginl = 0;
    unsigned short* gwth = 0;
    unsigned short* gwtl = 0;
    unsigned short* gqh = 0;
    unsigned short* gql = 0;
    unsigned short* gkh = 0;
    unsigned short* gkl = 0;
    unsigned short* gvth = 0;
    unsigned short* gvtl = 0;
    unsigned short* gph = 0;
    unsigned short* gpl = 0;
    cudaGetSymbolAddress((void**)&gf32, g_f32);
    cudaGetSymbolAddress((void**)&gS,   g_S);
    cudaGetSymbolAddress((void**)&ginh, g_inhi);
    cudaGetSymbolAddress((void**)&ginl, g_inlo);
    cudaGetSymbolAddress((void**)&gwth, g_wthi);
    cudaGetSymbolAddress((void**)&gwtl, g_wtlo);
    cudaGetSymbolAddress((void**)&gqh,  g_qhi);
    cudaGetSymbolAddress((void**)&gql,  g_qlo);
    cudaGetSymbolAddress((void**)&gkh,  g_khi);
    cudaGetSymbolAddress((void**)&gkl,  g_klo);
    cudaGetSymbolAddress((void**)&gvth, g_vthi);
    cudaGetSymbolAddress((void**)&gvtl, g_vtlo);
    cudaGetSymbolAddress((void**)&gph,  g_phi);
    cudaGetSymbolAddress((void**)&gpl,  g_plo);

    const size_t nTok = (size_t)NTOK * DMODEL;            /* 4M elements */
    const long long partStride = (long long)NTOK * DMODEL; /* partial buffer stride */
    dim3 splitGrid((unsigned)((nTok + 255) / 256));
    dim3 wtGrid(32, 32);
    dim3 wtBlk(32, 8);
    dim3 projGrid(DMODEL / GBN, NTOK / GBM, 2);            /* KS=2 -> 1024 blocks */
    dim3 scoreGrid(SEQ / GBN, SEQ / GBM, NBH);             /* KS=1 */
    dim3 avGrid(1, SEQ / GBM, NBH * 4);                    /* KS=4 -> 2048 blocks */
    dim3 vtGrid(SEQ / 32, DKH / 32, NBH);
    dim3 combGrid((unsigned)((nTok + 255) / 256));

    /* Q projection: split-K partials -> combine (bias + 1/8 scale + split) */
    split_kernel<<<splitGrid, 256>>>(queries, ginh, ginl, 1.0f, nTok);
    wtrans_split<<<wtGrid, wtBlk>>>(Wq, gwth, gwtl);
    gemm_f16x3_nt<<<projGrid, 128>>>(ginh, ginl, gwth, gwtl, (const float*)0, (float*)0,
        (unsigned short*)0, (unsigned short*)0, 1.0f,
        DMODEL, DMODEL, DMODEL, DMODEL, 0LL, 0LL, 0LL, 0LL, 0LL, 0LL, 1,
        gS, partStride, 2);
    combine_kernel<<<combGrid, 256>>>(gS, partStride, 2, bq, DMODEL, 0.125f,
        (float*)0, gqh, gql, nTok);

    /* K projection */
    split_kernel<<<splitGrid, 256>>>(keys, ginh, ginl, 1.0f, nTok);
    wtrans_split<<<wtGrid, wtBlk>>>(Wk, gwth, gwtl);
    gemm_f16x3_nt<<<projGrid, 128>>>(ginh, ginl, gwth, gwtl, (const float*)0, (float*)0,
        (unsigned short*)0, (unsigned short*)0, 1.0f,
        DMODEL, DMODEL, DMODEL, DMODEL, 0LL, 0LL, 0LL, 0LL, 0LL, 0LL, 1,
        gS, partStride, 2);
    combine_kernel<<<combGrid, 256>>>(gS, partStride, 2, bk, DMODEL, 1.0f,
        (float*)0, gkh, gkl, nTok);

    /* V projection -> fp32 ctx buffer -> per-head transpose split */
    split_kernel<<<splitGrid, 256>>>(values, ginh, ginl, 1.0f, nTok);
    wtrans_split<<<wtGrid, wtBlk>>>(Wv, gwth, gwtl);
    gemm_f16x3_nt<<<projGrid, 128>>>(ginh, ginl, gwth, gwtl, (const float*)0, (float*)0,
        (unsigned short*)0, (unsigned short*)0, 1.0f,
        DMODEL, DMODEL, DMODEL, DMODEL, 0LL, 0LL, 0LL, 0LL, 0LL, 0LL, 1,
        gS, partStride, 2);
    combine_kernel<<<combGrid, 256>>>(gS, partStride, 2, bv, DMODEL, 1.0f,
        gf32, (unsigned short*)0, (unsigned short*)0, nTok);
    vtrans_split<<<vtGrid, wtBlk>>>(gf32, gvth, gvtl);

    /* scores: S[bh][q][k] = (Q/8) @ K^T  (KS=1, direct fp32) */
    gemm_f16x3_nt<<<scoreGrid, 128>>>(gqh, gql, gkh, gkl, (const float*)0, gS,
        (unsigned short*)0, (unsigned short*)0, 1.0f,
        DKH, DMODEL, DMODEL, SEQ,
        (long long)SEQ * DMODEL, (long long)DKH,
        (long long)SEQ * DMODEL, (long long)DKH,
        16LL * SEQ * SEQ, (long long)SEQ * SEQ, NHEADS,
        (float*)0, 0LL, 1);

    /* top-k + softmax -> P hi/lo */
    topk_softmax_kernel<<<NBH * SEQ, 256>>>(gS, gph, gpl);

    /* context = P @ V: split-K (KS=4) partials (gS is dead now) -> combine */
    gemm_f16x3_nt<<<avGrid, 128>>>(gph, gpl, gvth, gvtl, (const float*)0, (float*)0,
        (unsigned short*)0, (unsigned short*)0, 1.0f,
        SEQ, SEQ, SEQ, DMODEL,
        16LL * SEQ * SEQ, (long long)SEQ * SEQ,
        16LL * DKH * SEQ, (long long)DKH * SEQ,
        (long long)SEQ * DMODEL, (long long)DKH, NHEADS,
        gS, partStride, 4);
    combine_kernel<<<combGrid, 256>>>(gS, partStride, 4, (const float*)0, DMODEL, 1.0f,
        (float*)0, ginh, ginl, nTok);

    /* output projection: split-K partials -> combine (bias, fp32 out) */
    wtrans_split<<<wtGrid, wtBlk>>>(Wo, gwth, gwtl);
    gemm_f16x3_nt<<<projGrid, 128>>>(ginh, ginl, gwth, gwtl, (const float*)0, (float*)0,
        (unsigned short*)0, (unsigned short*)0, 1.0f,
        DMODEL, DMODEL, DMODEL, DMODEL, 0LL, 0LL, 0LL, 0LL, 0LL, 0LL, 1,
        gS, partStride, 2);
    combine_kernel<<<combGrid, 256>>>(gS, partStride, 2, bo, DMODEL, 1.0f,
        out, (unsigned short*)0, (unsigned short*)0, nTok);
}